// round 16
// baseline (speedup 1.0000x reference)
#include <cuda_runtime.h>
#include <math.h>
#include <stdint.h>

#define NB 4
#define NN 4096
#define NC 256
#define NK 100

// ---------------- scratch ----------------
__device__ float g_img[16 * 256 * 4096];
__device__ float g_h  [16 * 256 * 4096];
__device__ float g_cz [16 * 100 * 4096];
__device__ uint32_t g_img2[16 * 128 * 4096];
__device__ uint32_t g_h2  [16 * 128 * 4096];
__device__ uint32_t g_w1t2[49 * 128 * 256];
__device__ uint32_t g_w2p2[128 * 256];
__device__ uint32_t g_w3p2[128 * 128];
__device__ float g_invs[1600];
__device__ float g_center[16 * 100 * 256];
__device__ float g_cin[400 * 256];
__device__ float g_kb [400 * 256];
__device__ float g_vb [400 * 256];
__device__ float g_qb [4 * 4096 * 256];
__device__ float g_ob [4 * 4096 * 256];
__device__ float g_outb[4 * 4096 * 256];

// ---------------- helpers ----------------
__device__ __forceinline__ float gelu_f(float x) {
    return 0.5f * x * (1.0f + erff(x * 0.70710678118654752440f));
}
__device__ __forceinline__ float sigmoid_f(float x) {
    return 1.0f / (1.0f + expf(-x));
}
__device__ __forceinline__ uint32_t packbf(float lo, float hi) {
    uint32_t r;
    asm("cvt.rn.bf16x2.f32 %0, %1, %2;" : "=r"(r) : "f"(hi), "f"(lo));
    return r;
}
__device__ __forceinline__ float tf32r(float x) {
    uint32_t u;
    asm("cvt.rna.tf32.f32 %0, %1;" : "=r"(u) : "f"(x));
    return __uint_as_float(u);
}
__device__ __forceinline__ uint32_t smem_u32(const void* p) {
    uint32_t a;
    asm("{ .reg .u64 t; cvta.to.shared.u64 t, %1; cvt.u32.u64 %0, t; }" : "=r"(a) : "l"(p));
    return a;
}
__device__ __forceinline__ void cp_async4(uint32_t dst, const void* src, int srcsize) {
    asm volatile("cp.async.ca.shared.global [%0], [%1], 4, %2;"
                 :: "r"(dst), "l"(src), "r"(srcsize));
}
__device__ __forceinline__ void cp_commit() {
    asm volatile("cp.async.commit_group;");
}
__device__ __forceinline__ void mma_bf16(float* c, uint32_t a0, uint32_t a1, uint32_t a2,
                                         uint32_t a3, uint32_t b0, uint32_t b1) {
    asm volatile(
        "mma.sync.aligned.m16n8k16.row.col.f32.bf16.bf16.f32 "
        "{%0,%1,%2,%3}, {%4,%5,%6,%7}, {%8,%9}, {%0,%1,%2,%3};"
        : "+f"(c[0]), "+f"(c[1]), "+f"(c[2]), "+f"(c[3])
        : "r"(a0), "r"(a1), "r"(a2), "r"(a3), "r"(b0), "r"(b1));
}
__device__ __forceinline__ void mma_tf32(float* c, uint32_t a0, uint32_t a1, uint32_t a2,
                                         uint32_t a3, uint32_t b0, uint32_t b1) {
    asm volatile(
        "mma.sync.aligned.m16n8k8.row.col.f32.tf32.tf32.f32 "
        "{%0,%1,%2,%3}, {%4,%5,%6,%7}, {%8,%9}, {%0,%1,%2,%3};"
        : "+f"(c[0]), "+f"(c[1]), "+f"(c[2]), "+f"(c[3])
        : "r"(a0), "r"(a1), "r"(a2), "r"(a3), "r"(b0), "r"(b1));
}
__device__ __forceinline__ float warpReduceSum(float v) {
#pragma unroll
    for (int o = 16; o > 0; o >>= 1) v += __shfl_xor_sync(0xffffffffu, v, o);
    return v;
}
__device__ __forceinline__ float blockReduceSum(float v, float* sh) {
    int lane = threadIdx.x & 31, w = threadIdx.x >> 5;
    int nw = blockDim.x >> 5;
    v = warpReduceSum(v);
    __syncthreads();
    if (lane == 0) sh[w] = v;
    __syncthreads();
    float r = 0.0f;
    for (int i = 0; i < nw; i++) r += sh[i];
    return r;
}

// ---------------- build img2 ----------------
__global__ void build_img2_kernel(const float* __restrict__ x, const float* __restrict__ mem,
                                  uint32_t* __restrict__ img2) {
    int g = blockIdx.z;
    int b = g >> 2, tau = g & 3;
    const float* src = (tau < 3) ? (mem + (size_t)(b * 3 + tau) * NN * NC)
                                 : (x + (size_t)b * NN * NC);
    uint32_t* dst = img2 + (size_t)g * 128 * 4096;
    __shared__ float tile[32][33];
    int r0 = blockIdx.x * 32, c0 = blockIdx.y * 32;
    int tx = threadIdx.x, ty = threadIdx.y;
#pragma unroll
    for (int i = 0; i < 32; i += 8)
        tile[ty + i][tx] = src[(size_t)(r0 + ty + i) * NC + c0 + tx];
    __syncthreads();
#pragma unroll
    for (int i = 0; i < 2; i++) {
        int ci2l = ty + 8 * i;
        float lo = tile[tx][2 * ci2l];
        float hi = tile[tx][2 * ci2l + 1];
        dst[(size_t)((c0 >> 1) + ci2l) * 4096 + r0 + tx] = packbf(lo, hi);
    }
}

// ---------------- w1 pack: coalesced via smem transpose ----------------
// CTA tile: 32 co x 8 ci x 49 taps. Reads contiguous, writes 128B-coalesced.
__global__ __launch_bounds__(256) void w1_pack_kernel(const float* __restrict__ w,
                                                      uint32_t* __restrict__ wt) {
    __shared__ float tile[32 * 8 * 49];   // 50176 B
    int co0 = blockIdx.x * 32;
    int ci0 = blockIdx.y * 8;
    int tid = threadIdx.x;
    for (int e = tid; e < 32 * 392; e += 256) {
        int co_l = e / 392;
        int rem = e - co_l * 392;
        tile[co_l * 392 + rem] = w[((size_t)(co0 + co_l) * 256 + ci0) * 49 + rem];
    }
    __syncthreads();
    for (int e = tid; e < 49 * 4 * 32; e += 256) {
        int tap = e >> 7;
        int rem = e & 127;
        int ci2_l = rem >> 5;
        int co_l = rem & 31;
        float lo = tile[co_l * 392 + (2 * ci2_l) * 49 + tap];
        float hi = tile[co_l * 392 + (2 * ci2_l + 1) * 49 + tap];
        wt[((size_t)tap * 128 + (ci0 >> 1) + ci2_l) * 256 + co0 + co_l] = packbf(lo, hi);
    }
}

// ---------------- w2/w3 pack (small) ----------------
__global__ void pack23_kernel(const float* __restrict__ w2, const float* __restrict__ w3,
                              uint32_t* __restrict__ wt2, uint32_t* __restrict__ wt3) {
    int idx = blockIdx.x * 256 + threadIdx.x;
    if (idx < 128 * 256) {
        int co = idx & 255;
        int ci2 = idx >> 8;
        wt2[idx] = packbf(w2[(size_t)co * 256 + 2 * ci2], w2[(size_t)co * 256 + 2 * ci2 + 1]);
    } else if (idx < 128 * 256 + 128 * 128) {
        int e = idx - 128 * 256;
        int co = e & 127;
        int ci2 = e >> 7;
        float lo = 0.0f, hi = 0.0f;
        if (co < 100) {
            lo = w3[(size_t)co * 256 + 2 * ci2];
            hi = w3[(size_t)co * 256 + 2 * ci2 + 1];
        }
        wt3[e] = packbf(lo, hi);
    }
}

// ---------------- conv1 (unchanged; clock probe at launch #4) ----------------
#define C1_INBUF (8 * 744)
#define C1_WBUF (7 * 8 * 72)
#define CONV1_SMEM ((2 * C1_INBUF + 2 * C1_WBUF) * 4)
__global__ __launch_bounds__(256, 2) void conv1_mma_kernel(
    const uint32_t* __restrict__ img2, const uint32_t* __restrict__ w1t2,
    const float* __restrict__ bias, uint32_t* __restrict__ h2) {
    extern __shared__ uint32_t smem_c1[];
    uint32_t* in_s = smem_c1;
    uint32_t* w_s = smem_c1 + 2 * C1_INBUF;
    uint32_t in_base = smem_u32(smem_c1);

    int co0 = blockIdx.x * 64;
    int y0 = blockIdx.y * 4;
    int g = blockIdx.z;
    int tid = threadIdx.x;
    int w = tid >> 5, lane = tid & 31;
    int wm = w >> 1;
    int wn = w & 1;
    int q = lane >> 2, r4 = lane & 3;

    float acc[4][4][4];
#pragma unroll
    for (int t = 0; t < 4; t++)
#pragma unroll
        for (int j = 0; j < 4; j++)
#pragma unroll
            for (int e = 0; e < 4; e++) acc[t][j][e] = 0.0f;

    const uint32_t* imgG = img2 + (size_t)g * 128 * 4096;

    auto issue_fill = [&](int c8, int buf) {
        uint32_t dstb = in_base + (uint32_t)buf * C1_INBUF * 4;
        for (int e = tid; e < 5600; e += 256) {
            int ci2 = e / 700;
            int rem = e - ci2 * 700;
            int rh = rem / 70;
            int c = rem - rh * 70;
            int y = y0 + rh - 3;
            int x = c - 3;
            bool ok = (y >= 0 && y < 64 && x >= 0 && x < 64);
            const uint32_t* src = ok ? (imgG + (size_t)(c8 + ci2) * 4096 + y * 64 + x) : imgG;
            cp_async4(dstb + (uint32_t)(ci2 * 744 + rh * 73 + c) * 4, src, ok ? 4 : 0);
        }
        cp_commit();
    };

    uint32_t pf[14];
    auto load_pf = [&](int dy, int c8) {
#pragma unroll
        for (int i = 0; i < 14; i++) {
            int e = tid + i * 256;
            int dx = e >> 9, ci2 = (e >> 6) & 7, co = e & 63;
            pf[i] = w1t2[((size_t)(dy * 7 + dx) * 128 + c8 + ci2) * 256 + co0 + co];
        }
    };
    auto store_pf = [&](uint32_t* wb) {
#pragma unroll
        for (int i = 0; i < 14; i++) {
            int e = tid + i * 256;
            int dx = e >> 9, ci2 = (e >> 6) & 7, co = e & 63;
            wb[(dx * 8 + ci2) * 72 + co] = pf[i];
        }
    };

    issue_fill(0, 0);
    load_pf(0, 0);

    for (int c8 = 0; c8 < 128; c8 += 8) {
        int buf = (c8 >> 3) & 1;
        const uint32_t* in_b = in_s + buf * C1_INBUF;
        __syncthreads();
        store_pf(w_s);
        if (c8 + 8 < 128) {
            issue_fill(c8 + 8, buf ^ 1);
            asm volatile("cp.async.wait_group 1;");
        } else {
            asm volatile("cp.async.wait_group 0;");
        }
        __syncthreads();

        for (int dy = 0; dy < 7; dy++) {
            uint32_t* wb = w_s + (dy & 1) * C1_WBUF;
            if (dy > 0) {
                store_pf(wb);
                __syncthreads();
            }
            if (dy < 6) load_pf(dy + 1, c8);
            else if (c8 + 8 < 128) load_pf(0, c8 + 8);

            int rh = wm + dy;
#pragma unroll
            for (int dx = 0; dx < 7; dx++) {
                uint32_t A[4][4];
#pragma unroll
                for (int t = 0; t < 4; t++) {
                    int ab = r4 * 744 + rh * 73 + 16 * t + q + dx;
                    A[t][0] = in_b[ab];
                    A[t][1] = in_b[ab + 8];
                    A[t][2] = in_b[ab + 4 * 744];
                    A[t][3] = in_b[ab + 4 * 744 + 8];
                }
#pragma unroll
                for (int j = 0; j < 4; j++) {
                    int bb2 = (dx * 8 + r4) * 72 + wn * 32 + 8 * j + q;
                    uint32_t B0 = wb[bb2];
                    uint32_t B1 = wb[bb2 + 4 * 72];
#pragma unroll
                    for (int t = 0; t < 4; t++)
                        mma_bf16(acc[t][j], A[t][0], A[t][1], A[t][2], A[t][3], B0, B1);
                }
            }
        }
    }

    int Y = y0 + wm;
#pragma unroll
    for (int j = 0; j < 4; j++) {
        int co_e = co0 + wn * 32 + 8 * j + 2 * r4;
        float b0v = bias[co_e], b1v = bias[co_e + 1];
        int co2 = (co0 >> 1) + wn * 16 + 4 * j + r4;
        uint32_t* op = h2 + ((size_t)g * 128 + co2) * 4096 + Y * 64;
#pragma unroll
        for (int t = 0; t < 4; t++) {
            int X0 = 16 * t + q;
            op[X0]     = packbf(gelu_f(acc[t][j][0] + b0v), gelu_f(acc[t][j][1] + b1v));
            op[X0 + 8] = packbf(gelu_f(acc[t][j][2] + b0v), gelu_f(acc[t][j][3] + b1v));
        }
    }
}

// ---------------- 1x1 channel GEMM: chunk=16 ci2, pointer-hoisted cp.async ----------------
#define G1_INBUF (16 * 264)
#define G1_WBUF (16 * 72)
template <int MODE>
__global__ __launch_bounds__(256, 2) void gemm1x1_bf16_kernel(
    const uint32_t* __restrict__ in2, const uint32_t* __restrict__ w2,
    const float* __restrict__ bias, void* outv, int wW) {
    __shared__ uint32_t in_s[2 * G1_INBUF];
    __shared__ uint32_t w_s[2 * G1_WBUF];
    uint32_t in_base = smem_u32(in_s);
    uint32_t w_base = smem_u32(w_s);

    int co0 = blockIdx.x * 64;
    int px0 = blockIdx.y * 256;
    int g = blockIdx.z;
    int tid = threadIdx.x;
    int w = tid >> 5, lane = tid & 31;
    int wm = w >> 1, wn = w & 1;
    int q = lane >> 2, r4 = lane & 3;

    float acc[4][4][4];
#pragma unroll
    for (int t = 0; t < 4; t++)
#pragma unroll
        for (int j = 0; j < 4; j++)
#pragma unroll
            for (int e = 0; e < 4; e++) acc[t][j][e] = 0.0f;

    const uint32_t* inP = in2 + (size_t)g * 128 * 4096 + px0 + tid;
    const uint32_t* wP[4];
    uint32_t wdst_off[4];
#pragma unroll
    for (int r = 0; r < 4; r++) {
        int e = tid + r * 256;
        int ci2 = e >> 6, co = e & 63;
        wP[r] = w2 + (size_t)ci2 * wW + co0 + co;
        wdst_off[r] = (uint32_t)(ci2 * 72 + co) * 4;
    }
    uint32_t in_dst[2] = {in_base + (uint32_t)tid * 4, in_base + (G1_INBUF + tid) * 4u};
    uint32_t w_dst[2] = {w_base, w_base + (uint32_t)G1_WBUF * 4};

    auto issue = [&](int buf) {
#pragma unroll
        for (int r = 0; r < 16; r++)
            cp_async4(in_dst[buf] + (uint32_t)(r * 264) * 4, inP + (size_t)r * 4096, 4);
#pragma unroll
        for (int r = 0; r < 4; r++)
            cp_async4(w_dst[buf] + wdst_off[r], wP[r], 4);
        cp_commit();
        inP += 16 * 4096;
#pragma unroll
        for (int r = 0; r < 4; r++) wP[r] += 16 * wW;
    };

    issue(0);

    for (int it = 0; it < 8; it++) {
        int buf = it & 1;
        __syncthreads();
        if (it + 1 < 8) {
            issue(buf ^ 1);
            asm volatile("cp.async.wait_group 1;");
        } else {
            asm volatile("cp.async.wait_group 0;");
        }
        __syncthreads();
#pragma unroll
        for (int sub = 0; sub < 2; sub++) {
            const uint32_t* in_b = in_s + buf * G1_INBUF + sub * 8 * 264;
            const uint32_t* w_b = w_s + buf * G1_WBUF + sub * 8 * 72;
            uint32_t A[4][4];
#pragma unroll
            for (int t = 0; t < 4; t++) {
                int ab = r4 * 264 + wm * 64 + 16 * t + q;
                A[t][0] = in_b[ab];
                A[t][1] = in_b[ab + 8];
                A[t][2] = in_b[ab + 4 * 264];
                A[t][3] = in_b[ab + 4 * 264 + 8];
            }
#pragma unroll
            for (int j = 0; j < 4; j++) {
                int bb = r4 * 72 + wn * 32 + 8 * j + q;
                uint32_t B0 = w_b[bb];
                uint32_t B1 = w_b[bb + 4 * 72];
#pragma unroll
                for (int t = 0; t < 4; t++)
                    mma_bf16(acc[t][j], A[t][0], A[t][1], A[t][2], A[t][3], B0, B1);
            }
        }
    }

    if (MODE == 0) {
        uint32_t* out2 = (uint32_t*)outv;
#pragma unroll
        for (int j = 0; j < 4; j++) {
            int co_e = co0 + wn * 32 + 8 * j + 2 * r4;
            float b0v = bias[co_e], b1v = bias[co_e + 1];
            int co2 = (co0 >> 1) + wn * 16 + 4 * j + r4;
            uint32_t* op = out2 + ((size_t)g * 128 + co2) * 4096 + px0 + wm * 64;
#pragma unroll
            for (int t = 0; t < 4; t++) {
                int X = 16 * t + q;
                op[X]     = packbf(gelu_f(acc[t][j][0] + b0v), gelu_f(acc[t][j][1] + b1v));
                op[X + 8] = packbf(gelu_f(acc[t][j][2] + b0v), gelu_f(acc[t][j][3] + b1v));
            }
        }
    } else {
        float* outf = (float*)outv;
#pragma unroll
        for (int j = 0; j < 4; j++) {
            int co_e = co0 + wn * 32 + 8 * j + 2 * r4;
            float* op0 = outf + ((size_t)g * 100 + co_e) * 4096 + px0 + wm * 64;
#pragma unroll
            for (int t = 0; t < 4; t++) {
                int X = 16 * t + q;
                if (co_e < 100) {
                    op0[X] = acc[t][j][0];
                    op0[X + 8] = acc[t][j][2];
                }
                if (co_e + 1 < 100) {
                    op0[4096 + X] = acc[t][j][1];
                    op0[4096 + X + 8] = acc[t][j][3];
                }
            }
        }
    }
}

// ======== pipelined tf32 GEMM family ========
__global__ __launch_bounds__(256) void gemm_nt32_kernel(
    const float* __restrict__ A, const float* __restrict__ B,
    const float* __restrict__ bias, float* __restrict__ C,
    int N, int K, float scale) {
    __shared__ float As[2][16 * 136];
    __shared__ float Bs[2][16 * 72];
    int row0 = blockIdx.y * 128, col0 = blockIdx.x * 64;
    int tid = threadIdx.x;
    int w = tid >> 5, lane = tid & 31;
    int wm = w >> 1, wn = w & 1;
    int q = lane >> 2, r4 = lane & 3;
    int am = tid >> 2, akq = (tid & 3) * 4;
    int bn = tid >> 2, bkq = (tid & 3) * 4;

    float acc[2][4][4];
#pragma unroll
    for (int t = 0; t < 2; t++)
#pragma unroll
        for (int j = 0; j < 4; j++)
#pragma unroll
            for (int e = 0; e < 4; e++) acc[t][j][e] = 0.0f;

    float4 av0, av1, bv;
    auto load = [&](int k0) {
        av0 = *(const float4*)(A + (size_t)(row0 + am) * K + k0 + akq);
        av1 = *(const float4*)(A + (size_t)(row0 + am + 64) * K + k0 + akq);
        bv  = *(const float4*)(B + (size_t)(col0 + bn) * K + k0 + bkq);
    };
    auto store = [&](int p) {
        float* Ap = As[p];
        float* Bp = Bs[p];
        Ap[(akq + 0) * 136 + am] = tf32r(av0.x);
        Ap[(akq + 1) * 136 + am] = tf32r(av0.y);
        Ap[(akq + 2) * 136 + am] = tf32r(av0.z);
        Ap[(akq + 3) * 136 + am] = tf32r(av0.w);
        Ap[(akq + 0) * 136 + am + 64] = tf32r(av1.x);
        Ap[(akq + 1) * 136 + am + 64] = tf32r(av1.y);
        Ap[(akq + 2) * 136 + am + 64] = tf32r(av1.z);
        Ap[(akq + 3) * 136 + am + 64] = tf32r(av1.w);
        Bp[(bkq + 0) * 72 + bn] = tf32r(bv.x);
        Bp[(bkq + 1) * 72 + bn] = tf32r(bv.y);
        Bp[(bkq + 2) * 72 + bn] = tf32r(bv.z);
        Bp[(bkq + 3) * 72 + bn] = tf32r(bv.w);
    };

    load(0);
    store(0);
    __syncthreads();
    int p = 0;
    for (int k0 = 0; k0 < K; k0 += 16) {
        bool nxt = (k0 + 16 < K);
        if (nxt) load(k0 + 16);
        const uint32_t* As_u = (const uint32_t*)As[p];
        const uint32_t* Bs_u = (const uint32_t*)Bs[p];
#pragma unroll
        for (int s = 0; s < 2; s++) {
            int kk = s * 8;
            uint32_t a[2][4];
#pragma unroll
            for (int t = 0; t < 2; t++) {
                int mb = wm * 32 + 16 * t + q;
                a[t][0] = As_u[(kk + r4) * 136 + mb];
                a[t][1] = As_u[(kk + r4) * 136 + mb + 8];
                a[t][2] = As_u[(kk + r4 + 4) * 136 + mb];
                a[t][3] = As_u[(kk + r4 + 4) * 136 + mb + 8];
            }
#pragma unroll
            for (int j = 0; j < 4; j++) {
                int nb = wn * 32 + 8 * j + q;
                uint32_t b0 = Bs_u[(kk + r4) * 72 + nb];
                uint32_t b1 = Bs_u[(kk + r4 + 4) * 72 + nb];
#pragma unroll
                for (int t = 0; t < 2; t++)
                    mma_tf32(acc[t][j], a[t][0], a[t][1], a[t][2], a[t][3], b0, b1);
            }
        }
        if (nxt) {
            store(p ^ 1);
            __syncthreads();
        }
        p ^= 1;
    }
#pragma unroll
    for (int t = 0; t < 2; t++) {
#pragma unroll
        for (int j = 0; j < 4; j++) {
            int m0 = row0 + wm * 32 + 16 * t + q;
            int n0 = col0 + wn * 32 + 8 * j + 2 * r4;
            float b0v = bias[n0], b1v = bias[n0 + 1];
            C[(size_t)m0 * N + n0]           = (acc[t][j][0] + b0v) * scale;
            C[(size_t)m0 * N + n0 + 1]       = (acc[t][j][1] + b1v) * scale;
            C[(size_t)(m0 + 8) * N + n0]     = (acc[t][j][2] + b0v) * scale;
            C[(size_t)(m0 + 8) * N + n0 + 1] = (acc[t][j][3] + b1v) * scale;
        }
    }
}

__global__ __launch_bounds__(256) void gemm_nt32_bm_kernel(
    const float* __restrict__ A, const float* __restrict__ B,
    const float* __restrict__ bias, float* __restrict__ C,
    int N, int K) {
    __shared__ float As[2][16 * 136];
    __shared__ float Bs[2][16 * 72];
    int row0 = blockIdx.y * 128, col0 = blockIdx.x * 64;
    int tid = threadIdx.x;
    int w = tid >> 5, lane = tid & 31;
    int wm = w >> 1, wn = w & 1;
    int q = lane >> 2, r4 = lane & 3;
    int am = tid >> 2, akq = (tid & 3) * 4;
    int bn = tid >> 2, bkq = (tid & 3) * 4;

    float acc[2][4][4];
#pragma unroll
    for (int t = 0; t < 2; t++)
#pragma unroll
        for (int j = 0; j < 4; j++)
#pragma unroll
            for (int e = 0; e < 4; e++) acc[t][j][e] = 0.0f;

    float4 av0, av1, bv;
    auto load = [&](int k0) {
        av0 = *(const float4*)(A + (size_t)(row0 + am) * K + k0 + akq);
        av1 = *(const float4*)(A + (size_t)(row0 + am + 64) * K + k0 + akq);
        bv  = *(const float4*)(B + (size_t)(col0 + bn) * K + k0 + bkq);
    };
    auto store = [&](int p) {
        float* Ap = As[p];
        float* Bp = Bs[p];
        Ap[(akq + 0) * 136 + am] = tf32r(av0.x);
        Ap[(akq + 1) * 136 + am] = tf32r(av0.y);
        Ap[(akq + 2) * 136 + am] = tf32r(av0.z);
        Ap[(akq + 3) * 136 + am] = tf32r(av0.w);
        Ap[(akq + 0) * 136 + am + 64] = tf32r(av1.x);
        Ap[(akq + 1) * 136 + am + 64] = tf32r(av1.y);
        Ap[(akq + 2) * 136 + am + 64] = tf32r(av1.z);
        Ap[(akq + 3) * 136 + am + 64] = tf32r(av1.w);
        Bp[(bkq + 0) * 72 + bn] = tf32r(bv.x);
        Bp[(bkq + 1) * 72 + bn] = tf32r(bv.y);
        Bp[(bkq + 2) * 72 + bn] = tf32r(bv.z);
        Bp[(bkq + 3) * 72 + bn] = tf32r(bv.w);
    };

    load(0);
    store(0);
    __syncthreads();
    int p = 0;
    for (int k0 = 0; k0 < K; k0 += 16) {
        bool nxt = (k0 + 16 < K);
        if (nxt) load(k0 + 16);
        const uint32_t* As_u = (const uint32_t*)As[p];
        const uint32_t* Bs_u = (const uint32_t*)Bs[p];
#pragma unroll
        for (int s = 0; s < 2; s++) {
            int kk = s * 8;
            uint32_t a[2][4];
#pragma unroll
            for (int t = 0; t < 2; t++) {
                int mb = wm * 32 + 16 * t + q;
                a[t][0] = As_u[(kk + r4) * 136 + mb];
                a[t][1] = As_u[(kk + r4) * 136 + mb + 8];
                a[t][2] = As_u[(kk + r4 + 4) * 136 + mb];
                a[t][3] = As_u[(kk + r4 + 4) * 136 + mb + 8];
            }
#pragma unroll
            for (int j = 0; j < 4; j++) {
                int nb = wn * 32 + 8 * j + q;
                uint32_t b0 = Bs_u[(kk + r4) * 72 + nb];
                uint32_t b1 = Bs_u[(kk + r4 + 4) * 72 + nb];
#pragma unroll
                for (int t = 0; t < 2; t++)
                    mma_tf32(acc[t][j], a[t][0], a[t][1], a[t][2], a[t][3], b0, b1);
            }
        }
        if (nxt) {
            store(p ^ 1);
            __syncthreads();
        }
        p ^= 1;
    }
#pragma unroll
    for (int t = 0; t < 2; t++) {
#pragma unroll
        for (int j = 0; j < 4; j++) {
            int m0 = row0 + wm * 32 + 16 * t + q;
            int n0 = col0 + wn * 32 + 8 * j + 2 * r4;
            float bm0 = bias[m0], bm8 = bias[m0 + 8];
            C[(size_t)m0 * N + n0]           = acc[t][j][0] + bm0;
            C[(size_t)m0 * N + n0 + 1]       = acc[t][j][1] + bm0;
            C[(size_t)(m0 + 8) * N + n0]     = acc[t][j][2] + bm8;
            C[(size_t)(m0 + 8) * N + n0 + 1] = acc[t][j][3] + bm8;
        }
    }
}

__global__ __launch_bounds__(256) void gemm_nt32_km_kernel(
    const float* __restrict__ A, const float* __restrict__ B,
    const float* __restrict__ bias, float* __restrict__ C,
    int N, int K, int Mtot) {
    __shared__ float As[2][16 * 136];
    __shared__ float Bs[2][16 * 72];
    int row0 = blockIdx.y * 128, col0 = blockIdx.x * 64;
    const float* Ab = A + row0;
    int tid = threadIdx.x;
    int w = tid >> 5, lane = tid & 31;
    int wm = w >> 1, wn = w & 1;
    int q = lane >> 2, r4 = lane & 3;
    int ak = tid >> 5, amq = (tid & 31) << 2;
    int bn = tid >> 2, bkq = (tid & 3) * 4;

    float acc[2][4][4];
#pragma unroll
    for (int t = 0; t < 2; t++)
#pragma unroll
        for (int j = 0; j < 4; j++)
#pragma unroll
            for (int e = 0; e < 4; e++) acc[t][j][e] = 0.0f;

    float4 av0, av1, bv;
    auto load = [&](int k0) {
        av0 = *(const float4*)(Ab + (size_t)(k0 + ak) * Mtot + amq);
        av1 = *(const float4*)(Ab + (size_t)(k0 + ak + 8) * Mtot + amq);
        bv  = *(const float4*)(B + (size_t)(col0 + bn) * K + k0 + bkq);
    };
    auto store = [&](int p) {
        float* Ap = As[p];
        float* Bp = Bs[p];
        Ap[ak * 136 + amq + 0] = tf32r(av0.x);
        Ap[ak * 136 + amq + 1] = tf32r(av0.y);
        Ap[ak * 136 + amq + 2] = tf32r(av0.z);
        Ap[ak * 136 + amq + 3] = tf32r(av0.w);
        Ap[(ak + 8) * 136 + amq + 0] = tf32r(av1.x);
        Ap[(ak + 8) * 136 + amq + 1] = tf32r(av1.y);
        Ap[(ak + 8) * 136 + amq + 2] = tf32r(av1.z);
        Ap[(ak + 8) * 136 + amq + 3] = tf32r(av1.w);
        Bp[(bkq + 0) * 72 + bn] = tf32r(bv.x);
        Bp[(bkq + 1) * 72 + bn] = tf32r(bv.y);
        Bp[(bkq + 2) * 72 + bn] = tf32r(bv.z);
        Bp[(bkq + 3) * 72 + bn] = tf32r(bv.w);
    };

    load(0);
    store(0);
    __syncthreads();
    int p = 0;
    for (int k0 = 0; k0 < K; k0 += 16) {
        bool nxt = (k0 + 16 < K);
        if (nxt) load(k0 + 16);
        const uint32_t* As_u = (const uint32_t*)As[p];
        const uint32_t* Bs_u = (const uint32_t*)Bs[p];
#pragma unroll
        for (int s = 0; s < 2; s++) {
            int kk = s * 8;
            uint32_t a[2][4];
#pragma unroll
            for (int t = 0; t < 2; t++) {
                int mb = wm * 32 + 16 * t + q;
                a[t][0] = As_u[(kk + r4) * 136 + mb];
                a[t][1] = As_u[(kk + r4) * 136 + mb + 8];
                a[t][2] = As_u[(kk + r4 + 4) * 136 + mb];
                a[t][3] = As_u[(kk + r4 + 4) * 136 + mb + 8];
            }
#pragma unroll
            for (int j = 0; j < 4; j++) {
                int nb = wn * 32 + 8 * j + q;
                uint32_t b0 = Bs_u[(kk + r4) * 72 + nb];
                uint32_t b1 = Bs_u[(kk + r4 + 4) * 72 + nb];
#pragma unroll
                for (int t = 0; t < 2; t++)
                    mma_tf32(acc[t][j], a[t][0], a[t][1], a[t][2], a[t][3], b0, b1);
            }
        }
        if (nxt) {
            store(p ^ 1);
            __syncthreads();
        }
        p ^= 1;
    }
#pragma unroll
    for (int t = 0; t < 2; t++) {
#pragma unroll
        for (int j = 0; j < 4; j++) {
            int m0 = row0 + wm * 32 + 16 * t + q;
            int n0 = col0 + wn * 32 + 8 * j + 2 * r4;
            float b0v = bias[n0], b1v = bias[n0 + 1];
            C[(size_t)m0 * N + n0]           = acc[t][j][0] + b0v;
            C[(size_t)m0 * N + n0 + 1]       = acc[t][j][1] + b1v;
            C[(size_t)(m0 + 8) * N + n0]     = acc[t][j][2] + b0v;
            C[(size_t)(m0 + 8) * N + n0 + 1] = acc[t][j][3] + b1v;
        }
    }
}

// ---- center32: depth-2 register pipeline (256 k-iters, 64 CTAs: latency-exposed) ----
__global__ __launch_bounds__(256) void gemm_center32_kernel(
    const float* __restrict__ cz, const float* __restrict__ x,
    const float* __restrict__ mem, const float* __restrict__ invs,
    float* __restrict__ center) {
    int z = blockIdx.z;
    int b = z >> 2, tau = z & 3;
    const float* A = cz + (size_t)z * 100 * 4096;
    const float* B = (tau < 3) ? (mem + (size_t)(b * 3 + tau) * NN * NC)
                               : (x + (size_t)b * NN * NC);
    float* C = center + (size_t)z * 100 * 256;
    int col0 = blockIdx.x * 64;
    __shared__ float As[2][16 * 136];
    __shared__ float Bs[2][16 * 72];
    int tid = threadIdx.x;
    int w = tid >> 5, lane = tid & 31;
    int wm = w >> 1, wn = w & 1;
    int q = lane >> 2, r4 = lane & 3;
    int am = tid >> 2, akq = (tid & 3) * 4;
    bool a0ok = (am < 100), a1ok = (am + 64 < 100);
    int bk = tid >> 4, bnq = (tid & 15) * 4;

    float acc[2][4][4];
#pragma unroll
    for (int t = 0; t < 2; t++)
#pragma unroll
        for (int j = 0; j < 4; j++)
#pragma unroll
            for (int e = 0; e < 4; e++) acc[t][j][e] = 0.0f;

    float4 av0[2], av1[2], bv[2];
    auto load = [&](int k0, int s) {
        av0[s] = a0ok ? *(const float4*)(A + (size_t)am * 4096 + k0 + akq) : make_float4(0, 0, 0, 0);
        av1[s] = a1ok ? *(const float4*)(A + (size_t)(am + 64) * 4096 + k0 + akq) : make_float4(0, 0, 0, 0);
        bv[s]  = *(const float4*)(B + (size_t)(k0 + bk) * 256 + col0 + bnq);
    };
    auto store = [&](int p, int s) {
        float* Ap = As[p];
        float* Bp = Bs[p];
        Ap[(akq + 0) * 136 + am] = tf32r(av0[s].x);
        Ap[(akq + 1) * 136 + am] = tf32r(av0[s].y);
        Ap[(akq + 2) * 136 + am] = tf32r(av0[s].z);
        Ap[(akq + 3) * 136 + am] = tf32r(av0[s].w);
        Ap[(akq + 0) * 136 + am + 64] = tf32r(av1[s].x);
        Ap[(akq + 1) * 136 + am + 64] = tf32r(av1[s].y);
        Ap[(akq + 2) * 136 + am + 64] = tf32r(av1[s].z);
        Ap[(akq + 3) * 136 + am + 64] = tf32r(av1[s].w);
        Bp[bk * 72 + bnq + 0] = tf32r(bv[s].x);
        Bp[bk * 72 + bnq + 1] = tf32r(bv[s].y);
        Bp[bk * 72 + bnq + 2] = tf32r(bv[s].z);
        Bp[bk * 72 + bnq + 3] = tf32r(bv[s].w);
    };

    load(0, 0);
    store(0, 0);
    load(16, 1);
    __syncthreads();
    int p = 0;
    for (int it = 0; it < 256; it++) {
        int k0 = it << 4;
        if (it + 2 < 256) load(k0 + 32, it & 1);
        const uint32_t* As_u = (const uint32_t*)As[p];
        const uint32_t* Bs_u = (const uint32_t*)Bs[p];
#pragma unroll
        for (int s = 0; s < 2; s++) {
            int kk = s * 8;
            uint32_t a[2][4];
#pragma unroll
            for (int t = 0; t < 2; t++) {
                int mb = wm * 32 + 16 * t + q;
                a[t][0] = As_u[(kk + r4) * 136 + mb];
                a[t][1] = As_u[(kk + r4) * 136 + mb + 8];
                a[t][2] = As_u[(kk + r4 + 4) * 136 + mb];
                a[t][3] = As_u[(kk + r4 + 4) * 136 + mb + 8];
            }
#pragma unroll
            for (int j = 0; j < 4; j++) {
                int nb = wn * 32 + 8 * j + q;
                uint32_t b0 = Bs_u[(kk + r4) * 72 + nb];
                uint32_t b1 = Bs_u[(kk + r4 + 4) * 72 + nb];
#pragma unroll
                for (int t = 0; t < 2; t++)
                    mma_tf32(acc[t][j], a[t][0], a[t][1], a[t][2], a[t][3], b0, b1);
            }
        }
        if (it + 1 < 256) {
            store(p ^ 1, (it + 1) & 1);
            __syncthreads();
        }
        p ^= 1;
    }
#pragma unroll
    for (int t = 0; t < 2; t++) {
#pragma unroll
        for (int j = 0; j < 4; j++) {
            int m0 = wm * 32 + 16 * t + q;
            int n0 = col0 + wn * 32 + 8 * j + 2 * r4;
            if (m0 < 100) {
                float iv = invs[z * 100 + m0];
                C[(size_t)m0 * 256 + n0]     = acc[t][j][0] * iv;
                C[(size_t)m0 * 256 + n0 + 1] = acc[t][j][1] * iv;
            }
            if (m0 + 8 < 100) {
                float iv = invs[z * 100 + m0 + 8];
                C[(size_t)(m0 + 8) * 256 + n0]     = acc[t][j][2] * iv;
                C[(size_t)(m0 + 8) * 256 + n0 + 1] = acc[t][j][3] * iv;
            }
        }
    }
}

// ---------------- k/v merged fp32 GEMM ----------------
__global__ __launch_bounds__(256) void gemm_nt_kv_kernel(
    const float* __restrict__ A, const float* __restrict__ kw,
    const float* __restrict__ kbias, const float* __restrict__ vw,
    const float* __restrict__ vbias, float* __restrict__ Ck, float* __restrict__ Cv) {
    const float* B = blockIdx.z ? vw : kw;
    const float* bias = blockIdx.z ? vbias : kbias;
    float* C = blockIdx.z ? Cv : Ck;
    const int M = 400, N = 256, K = 256;
    __shared__ float As[16][68];
    __shared__ float Bs[16][68];
    int tid = threadIdx.x;
    int tx = tid & 15, ty = tid >> 4;
    int row0 = blockIdx.y * 64, col0 = blockIdx.x * 64;
    int lr = tid >> 2;
    int lk = (tid & 3) << 2;
    const float* Aptr = A + (size_t)(row0 + lr) * K + lk;
    const float* Bptr = B + (size_t)(col0 + lr) * K + lk;
    bool aok = (row0 + lr) < M;
    float acc[4][4];
#pragma unroll
    for (int i = 0; i < 4; i++)
#pragma unroll
        for (int j = 0; j < 4; j++) acc[i][j] = 0.0f;

    for (int k0 = 0; k0 < K; k0 += 16) {
        float4 av = aok ? *(const float4*)(Aptr + k0) : make_float4(0, 0, 0, 0);
        float4 bv = *(const float4*)(Bptr + k0);
        As[lk + 0][lr] = av.x; As[lk + 1][lr] = av.y; As[lk + 2][lr] = av.z; As[lk + 3][lr] = av.w;
        Bs[lk + 0][lr] = bv.x; Bs[lk + 1][lr] = bv.y; Bs[lk + 2][lr] = bv.z; Bs[lk + 3][lr] = bv.w;
        __syncthreads();
#pragma unroll
        for (int kk = 0; kk < 16; kk++) {
            float4 a = *(const float4*)&As[kk][ty * 4];
            float4 b = *(const float4*)&Bs[kk][tx * 4];
            float aa[4] = {a.x, a.y, a.z, a.w};
            float bb[4] = {b.x, b.y, b.z, b.w};
#pragma unroll
            for (int i = 0; i < 4; i++)
#pragma unroll
                for (int j = 0; j < 4; j++) acc[i][j] += aa[i] * bb[j];
        }
        __syncthreads();
    }
#pragma unroll
    for (int i = 0; i < 4; i++) {
        int m = row0 + ty * 4 + i;
        if (m < M) {
#pragma unroll
            for (int j = 0; j < 4; j++) {
                int n = col0 + tx * 4 + j;
                C[(size_t)m * N + n] = acc[i][j] + bias[n];
            }
        }
    }
}

// ---------------- softmax: single pass ----------------
__global__ void softmax_exp_kernel(float* __restrict__ data, float* __restrict__ invs) {
    __shared__ float sh[8];
    float4* row = (float4*)(data + (size_t)blockIdx.x * 4096);
    int tid = threadIdx.x;
    float s = 0.0f;
    for (int i = tid; i < 1024; i += 256) {
        float4 v = row[i];
        v.x = __expf(v.x);
        v.y = __expf(v.y);
        v.z = __expf(v.z);
        v.w = __expf(v.w);
        row[i] = v;
        s += v.x + v.y + v.z + v.w;
    }
    s = blockReduceSum(s, sh);
    if (tid == 0) invs[blockIdx.x] = 1.0f / s;
}

// ---------------- cosine gating + C_in + LN ----------------
__global__ void cos_cin_kernel(const float* __restrict__ center,
                               const float* __restrict__ alpha, const float* __restrict__ beta,
                               const float* __restrict__ lnw, const float* __restrict__ lnb,
                               float* __restrict__ cin) {
    __shared__ float sh[8];
    int bk = blockIdx.x;
    int b = bk / 100, k = bk - b * 100;
    int c = threadIdx.x;
    const float* base = center + ((size_t)b * 4 * 100 + k) * 256 + c;
    float p0 = base[0];
    float p1 = base[100 * 256];
    float p2 = base[2 * 100 * 256];
    float last = base[3 * 100 * 256];

    float nl = blockReduceSum(last * last, sh);
    float n0 = blockReduceSum(p0 * p0, sh);
    float n1 = blockReduceSum(p1 * p1, sh);
    float n2 = blockReduceSum(p2 * p2, sh);
    float d0 = blockReduceSum(last * p0, sh);
    float d1 = blockReduceSum(last * p1, sh);
    float d2 = blockReduceSum(last * p2, sh);

    float a = alpha[0], be = beta[0];
    float nls = sqrtf(nl);
    float c0 = sigmoid_f(be + a * (d0 / fmaxf(nls * sqrtf(n0), 1e-8f)));
    float c1 = sigmoid_f(be + a * (d1 / fmaxf(nls * sqrtf(n1), 1e-8f)));
    float c2 = sigmoid_f(be + a * (d2 / fmaxf(nls * sqrtf(n2), 1e-8f)));

    float v = last + c0 * p0 + c1 * p1 + c2 * p2;
    float mean = blockReduceSum(v, sh) * (1.0f / 256.0f);
    float d = v - mean;
    float var = blockReduceSum(d * d, sh) * (1.0f / 256.0f);
    cin[((size_t)b * 100 + k) * 256 + c] = d * rsqrtf(var + 1e-5f) * lnw[c] + lnb[c];
}

// ---------------- attention ----------------
__global__ __launch_bounds__(256) void attn_kernel(const float* __restrict__ q,
                                                   const float* __restrict__ k,
                                                   const float* __restrict__ v,
                                                   float* __restrict__ o) {
    __shared__ float ks[100 * 32];
    __shared__ float vs[100 * 32];
    int b = blockIdx.z, h = blockIdx.y;
    int n = blockIdx.x * 256 + threadIdx.x;
    int tid = threadIdx.x;
    for (int e = tid; e < 3200; e += 256) {
        int kk = e >> 5, d = e & 31;
        ks[kk * 32 + d] = k[((size_t)b * 100 + kk) * 256 + h * 32 + d];
        vs[kk * 32 + d] = v[((size_t)b * 100 + kk) * 256 + h * 32 + d];
    }
    __syncthreads();
    float qr[32];
    const float4* qp4 = (const float4*)(q + ((size_t)b * 4096 + n) * 256 + h * 32);
#pragma unroll
    for (int i = 0; i < 8; i++) {
        float4 vv = qp4[i];
        qr[4 * i] = vv.x; qr[4 * i + 1] = vv.y; qr[4 * i + 2] = vv.z; qr[4 * i + 3] = vv.w;
    }
    float m = -3.4e38f;
    for (int kk = 0; kk < 100; kk++) {
        float s = 0.0f;
#pragma unroll
        for (int d = 0; d < 32; d++) s += qr[d] * ks[kk * 32 + d];
        m = fmaxf(m, s);
    }
    float sum = 0.0f;
    float acc[32];
#pragma unroll
    for (int d = 0; d < 32; d++) acc[d] = 0.0f;
    for (int kk = 0; kk < 100; kk++) {
        float s = 0.0f;
#pragma unroll
        for (int d = 0; d < 32; d++) s += qr[d] * ks[kk * 32 + d];
        float e = __expf(s - m);
        sum += e;
#pragma unroll
        for (int d = 0; d < 32; d++) acc[d] += e * vs[kk * 32 + d];
    }
    float inv = 1.0f / sum;
    float4* op4 = (float4*)(o + ((size_t)b * 4096 + n) * 256 + h * 32);
#pragma unroll
    for (int i = 0; i < 8; i++)
        op4[i] = make_float4(acc[4 * i] * inv, acc[4 * i + 1] * inv,
                             acc[4 * i + 2] * inv, acc[4 * i + 3] * inv);
}

// ---------------- out = base + LN(p) ----------------
__global__ void add_ln_kernel(const float* __restrict__ base, const float* __restrict__ p,
                              const float* __restrict__ w, const float* __restrict__ bb,
                              float* __restrict__ out) {
    __shared__ float sh[8];
    int t = threadIdx.x;
    int lr = t >> 6;
    int cq = (t & 63) << 2;
    size_t row = (size_t)blockIdx.x * 4 + lr;
    int wid = t >> 5, lane = t & 31;

    float4 v = *(const float4*)(p + row * 256 + cq);
    float s = v.x + v.y + v.z + v.w;
    s = warpReduceSum(s);
    if (lane == 0) sh[wid] = s;
    __syncthreads();
    float mean = (sh[2 * lr] + sh[2 * lr + 1]) * (1.0f / 256.0f);
    float4 d;
    d.x = v.x - mean; d.y = v.y - mean; d.z = v.z - mean; d.w = v.w - mean;
    float ss = d.x * d.x + d.y * d.y + d.z * d.z + d.w * d.w;
    ss = warpReduceSum(ss);
    __syncthreads();
    if (lane == 0) sh[wid] = ss;
    __syncthreads();
    float var = (sh[2 * lr] + sh[2 * lr + 1]) * (1.0f / 256.0f);
    float inv = rsqrtf(var + 1e-5f);
    float4 wv = *(const float4*)(w + cq);
    float4 bv = *(const float4*)(bb + cq);
    float4 basev = *(const float4*)(base + row * 256 + cq);
    float4 r;
    r.x = basev.x + d.x * inv * wv.x + bv.x;
    r.y = basev.y + d.y * inv * wv.y + bv.y;
    r.z = basev.z + d.z * inv * wv.z + bv.z;
    r.w = basev.w + d.w * inv * wv.w + bv.w;
    *(float4*)(out + row * 256 + cq) = r;
}

// ---------------- depthwise 3x3 on (ch, B*4096): smem plane tile + float4 ----------------
__global__ __launch_bounds__(256) void dwconv_kernel(const float* __restrict__ in,
                                                     const float* __restrict__ w,
                                                     const float* __restrict__ bias,
                                                     float* __restrict__ out) {
    __shared__ float t[66 * 68];
    int plane = blockIdx.x;
    int ch = plane & 1023;
    int b = plane >> 10;
    const float* ip = in + (size_t)ch * 16384 + b * 4096;
    float* op = out + (size_t)ch * 16384 + b * 4096;
    int tid = threadIdx.x;

    float4 z4 = make_float4(0.f, 0.f, 0.f, 0.f);
    for (int e = tid; e < 1122; e += 256) ((float4*)t)[e] = z4;
    __syncthreads();
#pragma unroll
    for (int i = 0; i < 4; i++) {
        int idx = tid + i * 256;
        int y = idx >> 4;
        int x4 = (idx & 15) << 2;
        float4 vv = *(const float4*)(ip + y * 64 + x4);
        float* dst = &t[(y + 1) * 68 + 1 + x4];
        dst[0] = vv.x; dst[1] = vv.y; dst[2] = vv.z; dst[3] = vv.w;
    }
    float wr[9];
#pragma unroll
    for (int i = 0; i < 9; i++) wr[i] = w[ch * 9 + i];
    float bi = bias[ch];
    __syncthreads();

#pragma unroll
    for (int i = 0; i < 4; i++) {
        int idx = tid + i * 256;
        int y = idx >> 4;
        int x4 = (idx & 15) << 2;
        float r[4];
#pragma unroll
        for (int j = 0; j < 4; j++) {
            int x = x4 + j;
            float s = bi;
#pragma unroll
            for (int dy = 0; dy < 3; dy++)
#pragma unroll
                for (int dx = 0; dx < 3; dx++)
                    s += t[(y + dy) * 68 + x + dx] * wr[dy * 3 + dx];
            r[j] = gelu_f(s);
        }
        *(float4*)(op + y * 64 + x4) = make_float4(r[0], r[1], r[2], r[3]);
    }
}

// ---------------- host launcher ----------------
extern "C" void kernel_launch(void* const* d_in, const int* in_sizes, int n_in,
                              void* d_out, int out_size) {
    const float* x       = (const float*)d_in[0];
    const float* mem     = (const float*)d_in[1];
    const float* conv1_w = (const float*)d_in[2];
    const float* conv1_b = (const float*)d_in[3];
    const float* conv2_w = (const float*)d_in[4];
    const float* conv2_b = (const float*)d_in[5];
    const float* conv3_w = (const float*)d_in[6];
    const float* sim_a   = (const float*)d_in[7];
    const float* sim_b   = (const float*)d_in[8];
    const float* ln_w    = (const float*)d_in[9];
    const float* ln_b    = (const float*)d_in[10];
    const float* q_w     = (const float*)d_in[11];
    const float* q_b     = (const float*)d_in[12];
    const float* k_w     = (const float*)d_in[13];
    const float* k_b     = (const float*)d_in[14];
    const float* v_w     = (const float*)d_in[15];
    const float* v_b     = (const float*)d_in[16];
    const float* proj_w  = (const float*)d_in[17];
    const float* proj_b  = (const float*)d_in[18];
    const float* fc1_w   = (const float*)d_in[19];
    const float* fc1_b   = (const float*)d_in[20];
    const float* dw_w    = (const float*)d_in[21];
    const float* dw_b    = (const float*)d_in[22];
    const float* fc2_w   = (const float*)d_in[23];
    const float* fc2_b   = (const float*)d_in[24];
    float* out = (float*)d_out;

    float *img, *h, *cz, *center, *cin, *kb, *vb, *qb, *ob, *outb, *invs;
    uint32_t *img2, *h2, *w1t2, *w2p2, *w3p2;
    cudaGetSymbolAddress((void**)&img, g_img);
    cudaGetSymbolAddress((void**)&h, g_h);
    cudaGetSymbolAddress((void**)&cz, g_cz);
    cudaGetSymbolAddress((void**)&img2, g_img2);
    cudaGetSymbolAddress((void**)&h2, g_h2);
    cudaGetSymbolAddress((void**)&w1t2, g_w1t2);
    cudaGetSymbolAddress((void**)&w2p2, g_w2p2);
    cudaGetSymbolAddress((void**)&w3p2, g_w3p2);
    cudaGetSymbolAddress((void**)&invs, g_invs);
    cudaGetSymbolAddress((void**)&center, g_center);
    cudaGetSymbolAddress((void**)&cin, g_cin);
    cudaGetSymbolAddress((void**)&kb, g_kb);
    cudaGetSymbolAddress((void**)&vb, g_vb);
    cudaGetSymbolAddress((void**)&qb, g_qb);
    cudaGetSymbolAddress((void**)&ob, g_ob);
    cudaGetSymbolAddress((void**)&outb, g_outb);

    // 1: w1 pack (coalesced), 2: w2/w3 pack, 3: input pack, 4: conv1 (clock probe)
    w1_pack_kernel<<<dim3(8, 32), 256>>>(conv1_w, w1t2);
    pack23_kernel<<<192, 256>>>(conv2_w, conv3_w, w2p2, w3p2);
    build_img2_kernel<<<dim3(128, 8, 16), dim3(32, 8)>>>(x, mem, img2);
    cudaFuncSetAttribute(conv1_mma_kernel, cudaFuncAttributeMaxDynamicSharedMemorySize, CONV1_SMEM);
    conv1_mma_kernel<<<dim3(4, 16, 16), 256, CONV1_SMEM>>>(img2, w1t2, conv1_b, h2);
    gemm1x1_bf16_kernel<0><<<dim3(4, 16, 16), 256>>>(h2, w2p2, conv2_b, (void*)img2, 256);
    gemm1x1_bf16_kernel<1><<<dim3(2, 16, 16), 256>>>(img2, w3p2, (const float*)0, (void*)cz, 128);
    softmax_exp_kernel<<<1600, 256>>>(cz, invs);
    gemm_center32_kernel<<<dim3(4, 1, 16), 256>>>(cz, x, mem, invs, center);
    cos_cin_kernel<<<400, 256>>>(center, sim_a, sim_b, ln_w, ln_b, cin);
    gemm_nt32_kernel<<<dim3(4, 128), 256>>>(x, q_w, q_b, qb, 256, 256, 0.17677669529663687f);
    gemm_nt_kv_kernel<<<dim3(4, 7, 2), 256>>>(cin, k_w, k_b, v_w, v_b, kb, vb);
    attn_kernel<<<dim3(16, 8, 4), 256>>>(qb, kb, vb, ob);
    gemm_nt32_kernel<<<dim3(4, 128), 256>>>(ob, proj_w, proj_b, qb, 256, 256, 1.0f);
    add_ln_kernel<<<4096, 256>>>(x, qb, ln_w, ln_b, outb);
    gemm_nt32_bm_kernel<<<dim3(256, 8), 256>>>(fc1_w, outb, fc1_b, h, 16384, 256);
    dwconv_kernel<<<4096, 256>>>(h, dw_w, dw_b, img);
    gemm_nt32_km_kernel<<<dim3(4, 128), 256>>>(img, fc2_w, fc2_b, qb, 256, 1024, 16384);
    add_ln_kernel<<<4096, 256>>>(outb, qb, ln_w, ln_b, out);
}

// round 17
// speedup vs baseline: 1.0578x; 1.0578x over previous
#include <cuda_runtime.h>
#include <math.h>
#include <stdint.h>

#define NB 4
#define NN 4096
#define NC 256
#define NK 100

// ---------------- scratch ----------------
__device__ float g_img[16 * 256 * 4096];
__device__ float g_h  [16 * 256 * 4096];
__device__ float g_cz [16 * 100 * 4096];
__device__ uint32_t g_img2[16 * 128 * 4096];
__device__ uint32_t g_h2  [16 * 128 * 4096];
__device__ uint32_t g_w1t2[49 * 128 * 256];
__device__ uint32_t g_w2p2[128 * 256];
__device__ uint32_t g_w3p2[128 * 128];
__device__ float g_invs[1600];
__device__ float g_center[16 * 100 * 256];
__device__ float g_cin[400 * 256];
__device__ float g_kb [400 * 256];
__device__ float g_vb [400 * 256];
__device__ float g_qb [4 * 4096 * 256];
__device__ float g_ob [4 * 4096 * 256];
__device__ float g_outb[4 * 4096 * 256];

// ---------------- helpers ----------------
__device__ __forceinline__ float gelu_f(float x) {
    return 0.5f * x * (1.0f + erff(x * 0.70710678118654752440f));
}
__device__ __forceinline__ float sigmoid_f(float x) {
    return 1.0f / (1.0f + expf(-x));
}
__device__ __forceinline__ uint32_t packbf(float lo, float hi) {
    uint32_t r;
    asm("cvt.rn.bf16x2.f32 %0, %1, %2;" : "=r"(r) : "f"(hi), "f"(lo));
    return r;
}
__device__ __forceinline__ float tf32r(float x) {
    uint32_t u;
    asm("cvt.rna.tf32.f32 %0, %1;" : "=r"(u) : "f"(x));
    return __uint_as_float(u);
}
__device__ __forceinline__ uint32_t smem_u32(const void* p) {
    uint32_t a;
    asm("{ .reg .u64 t; cvta.to.shared.u64 t, %1; cvt.u32.u64 %0, t; }" : "=r"(a) : "l"(p));
    return a;
}
__device__ __forceinline__ void cp_async4(uint32_t dst, const void* src, int srcsize) {
    asm volatile("cp.async.ca.shared.global [%0], [%1], 4, %2;"
                 :: "r"(dst), "l"(src), "r"(srcsize));
}
__device__ __forceinline__ void cp_commit() {
    asm volatile("cp.async.commit_group;");
}
__device__ __forceinline__ void mma_bf16(float* c, uint32_t a0, uint32_t a1, uint32_t a2,
                                         uint32_t a3, uint32_t b0, uint32_t b1) {
    asm volatile(
        "mma.sync.aligned.m16n8k16.row.col.f32.bf16.bf16.f32 "
        "{%0,%1,%2,%3}, {%4,%5,%6,%7}, {%8,%9}, {%0,%1,%2,%3};"
        : "+f"(c[0]), "+f"(c[1]), "+f"(c[2]), "+f"(c[3])
        : "r"(a0), "r"(a1), "r"(a2), "r"(a3), "r"(b0), "r"(b1));
}
__device__ __forceinline__ void mma_tf32(float* c, uint32_t a0, uint32_t a1, uint32_t a2,
                                         uint32_t a3, uint32_t b0, uint32_t b1) {
    asm volatile(
        "mma.sync.aligned.m16n8k8.row.col.f32.tf32.tf32.f32 "
        "{%0,%1,%2,%3}, {%4,%5,%6,%7}, {%8,%9}, {%0,%1,%2,%3};"
        : "+f"(c[0]), "+f"(c[1]), "+f"(c[2]), "+f"(c[3])
        : "r"(a0), "r"(a1), "r"(a2), "r"(a3), "r"(b0), "r"(b1));
}
__device__ __forceinline__ float warpReduceSum(float v) {
#pragma unroll
    for (int o = 16; o > 0; o >>= 1) v += __shfl_xor_sync(0xffffffffu, v, o);
    return v;
}
__device__ __forceinline__ float blockReduceSum(float v, float* sh) {
    int lane = threadIdx.x & 31, w = threadIdx.x >> 5;
    int nw = blockDim.x >> 5;
    v = warpReduceSum(v);
    __syncthreads();
    if (lane == 0) sh[w] = v;
    __syncthreads();
    float r = 0.0f;
    for (int i = 0; i < nw; i++) r += sh[i];
    return r;
}

// ---------------- build img2 ----------------
__global__ void build_img2_kernel(const float* __restrict__ x, const float* __restrict__ mem,
                                  uint32_t* __restrict__ img2) {
    int g = blockIdx.z;
    int b = g >> 2, tau = g & 3;
    const float* src = (tau < 3) ? (mem + (size_t)(b * 3 + tau) * NN * NC)
                                 : (x + (size_t)b * NN * NC);
    uint32_t* dst = img2 + (size_t)g * 128 * 4096;
    __shared__ float tile[32][33];
    int r0 = blockIdx.x * 32, c0 = blockIdx.y * 32;
    int tx = threadIdx.x, ty = threadIdx.y;
#pragma unroll
    for (int i = 0; i < 32; i += 8)
        tile[ty + i][tx] = src[(size_t)(r0 + ty + i) * NC + c0 + tx];
    __syncthreads();
#pragma unroll
    for (int i = 0; i < 2; i++) {
        int ci2l = ty + 8 * i;
        float lo = tile[tx][2 * ci2l];
        float hi = tile[tx][2 * ci2l + 1];
        dst[(size_t)((c0 >> 1) + ci2l) * 4096 + r0 + tx] = packbf(lo, hi);
    }
}

// ---------------- w1 pack: coalesced via smem transpose ----------------
__global__ __launch_bounds__(256) void w1_pack_kernel(const float* __restrict__ w,
                                                      uint32_t* __restrict__ wt) {
    __shared__ float tile[32 * 8 * 49];
    int co0 = blockIdx.x * 32;
    int ci0 = blockIdx.y * 8;
    int tid = threadIdx.x;
    for (int e = tid; e < 32 * 392; e += 256) {
        int co_l = e / 392;
        int rem = e - co_l * 392;
        tile[co_l * 392 + rem] = w[((size_t)(co0 + co_l) * 256 + ci0) * 49 + rem];
    }
    __syncthreads();
    for (int e = tid; e < 49 * 4 * 32; e += 256) {
        int tap = e >> 7;
        int rem = e & 127;
        int ci2_l = rem >> 5;
        int co_l = rem & 31;
        float lo = tile[co_l * 392 + (2 * ci2_l) * 49 + tap];
        float hi = tile[co_l * 392 + (2 * ci2_l + 1) * 49 + tap];
        wt[((size_t)tap * 128 + (ci0 >> 1) + ci2_l) * 256 + co0 + co_l] = packbf(lo, hi);
    }
}

// ---------------- w2/w3 pack ----------------
__global__ void pack23_kernel(const float* __restrict__ w2, const float* __restrict__ w3,
                              uint32_t* __restrict__ wt2, uint32_t* __restrict__ wt3) {
    int idx = blockIdx.x * 256 + threadIdx.x;
    if (idx < 128 * 256) {
        int co = idx & 255;
        int ci2 = idx >> 8;
        wt2[idx] = packbf(w2[(size_t)co * 256 + 2 * ci2], w2[(size_t)co * 256 + 2 * ci2 + 1]);
    } else if (idx < 128 * 256 + 128 * 128) {
        int e = idx - 128 * 256;
        int co = e & 127;
        int ci2 = e >> 7;
        float lo = 0.0f, hi = 0.0f;
        if (co < 100) {
            lo = w3[(size_t)co * 256 + 2 * ci2];
            hi = w3[(size_t)co * 256 + 2 * ci2 + 1];
        }
        wt3[e] = packbf(lo, hi);
    }
}

// ---------------- conv1 (unchanged; clock probe at launch #4) ----------------
#define C1_INBUF (8 * 744)
#define C1_WBUF (7 * 8 * 72)
#define CONV1_SMEM ((2 * C1_INBUF + 2 * C1_WBUF) * 4)
__global__ __launch_bounds__(256, 2) void conv1_mma_kernel(
    const uint32_t* __restrict__ img2, const uint32_t* __restrict__ w1t2,
    const float* __restrict__ bias, uint32_t* __restrict__ h2) {
    extern __shared__ uint32_t smem_c1[];
    uint32_t* in_s = smem_c1;
    uint32_t* w_s = smem_c1 + 2 * C1_INBUF;
    uint32_t in_base = smem_u32(smem_c1);

    int co0 = blockIdx.x * 64;
    int y0 = blockIdx.y * 4;
    int g = blockIdx.z;
    int tid = threadIdx.x;
    int w = tid >> 5, lane = tid & 31;
    int wm = w >> 1;
    int wn = w & 1;
    int q = lane >> 2, r4 = lane & 3;

    float acc[4][4][4];
#pragma unroll
    for (int t = 0; t < 4; t++)
#pragma unroll
        for (int j = 0; j < 4; j++)
#pragma unroll
            for (int e = 0; e < 4; e++) acc[t][j][e] = 0.0f;

    const uint32_t* imgG = img2 + (size_t)g * 128 * 4096;

    auto issue_fill = [&](int c8, int buf) {
        uint32_t dstb = in_base + (uint32_t)buf * C1_INBUF * 4;
        for (int e = tid; e < 5600; e += 256) {
            int ci2 = e / 700;
            int rem = e - ci2 * 700;
            int rh = rem / 70;
            int c = rem - rh * 70;
            int y = y0 + rh - 3;
            int x = c - 3;
            bool ok = (y >= 0 && y < 64 && x >= 0 && x < 64);
            const uint32_t* src = ok ? (imgG + (size_t)(c8 + ci2) * 4096 + y * 64 + x) : imgG;
            cp_async4(dstb + (uint32_t)(ci2 * 744 + rh * 73 + c) * 4, src, ok ? 4 : 0);
        }
        cp_commit();
    };

    uint32_t pf[14];
    auto load_pf = [&](int dy, int c8) {
#pragma unroll
        for (int i = 0; i < 14; i++) {
            int e = tid + i * 256;
            int dx = e >> 9, ci2 = (e >> 6) & 7, co = e & 63;
            pf[i] = w1t2[((size_t)(dy * 7 + dx) * 128 + c8 + ci2) * 256 + co0 + co];
        }
    };
    auto store_pf = [&](uint32_t* wb) {
#pragma unroll
        for (int i = 0; i < 14; i++) {
            int e = tid + i * 256;
            int dx = e >> 9, ci2 = (e >> 6) & 7, co = e & 63;
            wb[(dx * 8 + ci2) * 72 + co] = pf[i];
        }
    };

    issue_fill(0, 0);
    load_pf(0, 0);

    for (int c8 = 0; c8 < 128; c8 += 8) {
        int buf = (c8 >> 3) & 1;
        const uint32_t* in_b = in_s + buf * C1_INBUF;
        __syncthreads();
        store_pf(w_s);
        if (c8 + 8 < 128) {
            issue_fill(c8 + 8, buf ^ 1);
            asm volatile("cp.async.wait_group 1;");
        } else {
            asm volatile("cp.async.wait_group 0;");
        }
        __syncthreads();

        for (int dy = 0; dy < 7; dy++) {
            uint32_t* wb = w_s + (dy & 1) * C1_WBUF;
            if (dy > 0) {
                store_pf(wb);
                __syncthreads();
            }
            if (dy < 6) load_pf(dy + 1, c8);
            else if (c8 + 8 < 128) load_pf(0, c8 + 8);

            int rh = wm + dy;
#pragma unroll
            for (int dx = 0; dx < 7; dx++) {
                uint32_t A[4][4];
#pragma unroll
                for (int t = 0; t < 4; t++) {
                    int ab = r4 * 744 + rh * 73 + 16 * t + q + dx;
                    A[t][0] = in_b[ab];
                    A[t][1] = in_b[ab + 8];
                    A[t][2] = in_b[ab + 4 * 744];
                    A[t][3] = in_b[ab + 4 * 744 + 8];
                }
#pragma unroll
                for (int j = 0; j < 4; j++) {
                    int bb2 = (dx * 8 + r4) * 72 + wn * 32 + 8 * j + q;
                    uint32_t B0 = wb[bb2];
                    uint32_t B1 = wb[bb2 + 4 * 72];
#pragma unroll
                    for (int t = 0; t < 4; t++)
                        mma_bf16(acc[t][j], A[t][0], A[t][1], A[t][2], A[t][3], B0, B1);
                }
            }
        }
    }

    int Y = y0 + wm;
#pragma unroll
    for (int j = 0; j < 4; j++) {
        int co_e = co0 + wn * 32 + 8 * j + 2 * r4;
        float b0v = bias[co_e], b1v = bias[co_e + 1];
        int co2 = (co0 >> 1) + wn * 16 + 4 * j + r4;
        uint32_t* op = h2 + ((size_t)g * 128 + co2) * 4096 + Y * 64;
#pragma unroll
        for (int t = 0; t < 4; t++) {
            int X0 = 16 * t + q;
            op[X0]     = packbf(gelu_f(acc[t][j][0] + b0v), gelu_f(acc[t][j][1] + b1v));
            op[X0 + 8] = packbf(gelu_f(acc[t][j][2] + b0v), gelu_f(acc[t][j][3] + b1v));
        }
    }
}

// ---------------- 1x1 channel GEMM: chunk=16 ci2, pointer-hoisted cp.async ----------------
#define G1_INBUF (16 * 264)
#define G1_WBUF (16 * 72)
template <int MODE>
__global__ __launch_bounds__(256, 2) void gemm1x1_bf16_kernel(
    const uint32_t* __restrict__ in2, const uint32_t* __restrict__ w2,
    const float* __restrict__ bias, void* outv, int wW) {
    __shared__ uint32_t in_s[2 * G1_INBUF];
    __shared__ uint32_t w_s[2 * G1_WBUF];
    uint32_t in_base = smem_u32(in_s);
    uint32_t w_base = smem_u32(w_s);

    int co0 = blockIdx.x * 64;
    int px0 = blockIdx.y * 256;
    int g = blockIdx.z;
    int tid = threadIdx.x;
    int w = tid >> 5, lane = tid & 31;
    int wm = w >> 1, wn = w & 1;
    int q = lane >> 2, r4 = lane & 3;

    float acc[4][4][4];
#pragma unroll
    for (int t = 0; t < 4; t++)
#pragma unroll
        for (int j = 0; j < 4; j++)
#pragma unroll
            for (int e = 0; e < 4; e++) acc[t][j][e] = 0.0f;

    const uint32_t* inP = in2 + (size_t)g * 128 * 4096 + px0 + tid;
    const uint32_t* wP[4];
    uint32_t wdst_off[4];
#pragma unroll
    for (int r = 0; r < 4; r++) {
        int e = tid + r * 256;
        int ci2 = e >> 6, co = e & 63;
        wP[r] = w2 + (size_t)ci2 * wW + co0 + co;
        wdst_off[r] = (uint32_t)(ci2 * 72 + co) * 4;
    }
    uint32_t in_dst[2] = {in_base + (uint32_t)tid * 4, in_base + (G1_INBUF + tid) * 4u};
    uint32_t w_dst[2] = {w_base, w_base + (uint32_t)G1_WBUF * 4};

    auto issue = [&](int buf) {
#pragma unroll
        for (int r = 0; r < 16; r++)
            cp_async4(in_dst[buf] + (uint32_t)(r * 264) * 4, inP + (size_t)r * 4096, 4);
#pragma unroll
        for (int r = 0; r < 4; r++)
            cp_async4(w_dst[buf] + wdst_off[r], wP[r], 4);
        cp_commit();
        inP += 16 * 4096;
#pragma unroll
        for (int r = 0; r < 4; r++) wP[r] += 16 * wW;
    };

    issue(0);

    for (int it = 0; it < 8; it++) {
        int buf = it & 1;
        __syncthreads();
        if (it + 1 < 8) {
            issue(buf ^ 1);
            asm volatile("cp.async.wait_group 1;");
        } else {
            asm volatile("cp.async.wait_group 0;");
        }
        __syncthreads();
#pragma unroll
        for (int sub = 0; sub < 2; sub++) {
            const uint32_t* in_b = in_s + buf * G1_INBUF + sub * 8 * 264;
            const uint32_t* w_b = w_s + buf * G1_WBUF + sub * 8 * 72;
            uint32_t A[4][4];
#pragma unroll
            for (int t = 0; t < 4; t++) {
                int ab = r4 * 264 + wm * 64 + 16 * t + q;
                A[t][0] = in_b[ab];
                A[t][1] = in_b[ab + 8];
                A[t][2] = in_b[ab + 4 * 264];
                A[t][3] = in_b[ab + 4 * 264 + 8];
            }
#pragma unroll
            for (int j = 0; j < 4; j++) {
                int bb = r4 * 72 + wn * 32 + 8 * j + q;
                uint32_t B0 = w_b[bb];
                uint32_t B1 = w_b[bb + 4 * 72];
#pragma unroll
                for (int t = 0; t < 4; t++)
                    mma_bf16(acc[t][j], A[t][0], A[t][1], A[t][2], A[t][3], B0, B1);
            }
        }
    }

    if (MODE == 0) {
        uint32_t* out2 = (uint32_t*)outv;
#pragma unroll
        for (int j = 0; j < 4; j++) {
            int co_e = co0 + wn * 32 + 8 * j + 2 * r4;
            float b0v = bias[co_e], b1v = bias[co_e + 1];
            int co2 = (co0 >> 1) + wn * 16 + 4 * j + r4;
            uint32_t* op = out2 + ((size_t)g * 128 + co2) * 4096 + px0 + wm * 64;
#pragma unroll
            for (int t = 0; t < 4; t++) {
                int X = 16 * t + q;
                op[X]     = packbf(gelu_f(acc[t][j][0] + b0v), gelu_f(acc[t][j][1] + b1v));
                op[X + 8] = packbf(gelu_f(acc[t][j][2] + b0v), gelu_f(acc[t][j][3] + b1v));
            }
        }
    } else {
        float* outf = (float*)outv;
#pragma unroll
        for (int j = 0; j < 4; j++) {
            int co_e = co0 + wn * 32 + 8 * j + 2 * r4;
            float* op0 = outf + ((size_t)g * 100 + co_e) * 4096 + px0 + wm * 64;
#pragma unroll
            for (int t = 0; t < 4; t++) {
                int X = 16 * t + q;
                if (co_e < 100) {
                    op0[X] = acc[t][j][0];
                    op0[X + 8] = acc[t][j][2];
                }
                if (co_e + 1 < 100) {
                    op0[4096 + X] = acc[t][j][1];
                    op0[4096 + X + 8] = acc[t][j][3];
                }
            }
        }
    }
}

// ======== pipelined tf32 GEMM family ========
__global__ __launch_bounds__(256) void gemm_nt32_kernel(
    const float* __restrict__ A, const float* __restrict__ B,
    const float* __restrict__ bias, float* __restrict__ C,
    int N, int K, float scale) {
    __shared__ float As[2][16 * 136];
    __shared__ float Bs[2][16 * 72];
    int row0 = blockIdx.y * 128, col0 = blockIdx.x * 64;
    int tid = threadIdx.x;
    int w = tid >> 5, lane = tid & 31;
    int wm = w >> 1, wn = w & 1;
    int q = lane >> 2, r4 = lane & 3;
    int am = tid >> 2, akq = (tid & 3) * 4;
    int bn = tid >> 2, bkq = (tid & 3) * 4;

    float acc[2][4][4];
#pragma unroll
    for (int t = 0; t < 2; t++)
#pragma unroll
        for (int j = 0; j < 4; j++)
#pragma unroll
            for (int e = 0; e < 4; e++) acc[t][j][e] = 0.0f;

    float4 av0, av1, bv;
    auto load = [&](int k0) {
        av0 = *(const float4*)(A + (size_t)(row0 + am) * K + k0 + akq);
        av1 = *(const float4*)(A + (size_t)(row0 + am + 64) * K + k0 + akq);
        bv  = *(const float4*)(B + (size_t)(col0 + bn) * K + k0 + bkq);
    };
    auto store = [&](int p) {
        float* Ap = As[p];
        float* Bp = Bs[p];
        Ap[(akq + 0) * 136 + am] = tf32r(av0.x);
        Ap[(akq + 1) * 136 + am] = tf32r(av0.y);
        Ap[(akq + 2) * 136 + am] = tf32r(av0.z);
        Ap[(akq + 3) * 136 + am] = tf32r(av0.w);
        Ap[(akq + 0) * 136 + am + 64] = tf32r(av1.x);
        Ap[(akq + 1) * 136 + am + 64] = tf32r(av1.y);
        Ap[(akq + 2) * 136 + am + 64] = tf32r(av1.z);
        Ap[(akq + 3) * 136 + am + 64] = tf32r(av1.w);
        Bp[(bkq + 0) * 72 + bn] = tf32r(bv.x);
        Bp[(bkq + 1) * 72 + bn] = tf32r(bv.y);
        Bp[(bkq + 2) * 72 + bn] = tf32r(bv.z);
        Bp[(bkq + 3) * 72 + bn] = tf32r(bv.w);
    };

    load(0);
    store(0);
    __syncthreads();
    int p = 0;
    for (int k0 = 0; k0 < K; k0 += 16) {
        bool nxt = (k0 + 16 < K);
        if (nxt) load(k0 + 16);
        const uint32_t* As_u = (const uint32_t*)As[p];
        const uint32_t* Bs_u = (const uint32_t*)Bs[p];
#pragma unroll
        for (int s = 0; s < 2; s++) {
            int kk = s * 8;
            uint32_t a[2][4];
#pragma unroll
            for (int t = 0; t < 2; t++) {
                int mb = wm * 32 + 16 * t + q;
                a[t][0] = As_u[(kk + r4) * 136 + mb];
                a[t][1] = As_u[(kk + r4) * 136 + mb + 8];
                a[t][2] = As_u[(kk + r4 + 4) * 136 + mb];
                a[t][3] = As_u[(kk + r4 + 4) * 136 + mb + 8];
            }
#pragma unroll
            for (int j = 0; j < 4; j++) {
                int nb = wn * 32 + 8 * j + q;
                uint32_t b0 = Bs_u[(kk + r4) * 72 + nb];
                uint32_t b1 = Bs_u[(kk + r4 + 4) * 72 + nb];
#pragma unroll
                for (int t = 0; t < 2; t++)
                    mma_tf32(acc[t][j], a[t][0], a[t][1], a[t][2], a[t][3], b0, b1);
            }
        }
        if (nxt) {
            store(p ^ 1);
            __syncthreads();
        }
        p ^= 1;
    }
#pragma unroll
    for (int t = 0; t < 2; t++) {
#pragma unroll
        for (int j = 0; j < 4; j++) {
            int m0 = row0 + wm * 32 + 16 * t + q;
            int n0 = col0 + wn * 32 + 8 * j + 2 * r4;
            float b0v = bias[n0], b1v = bias[n0 + 1];
            C[(size_t)m0 * N + n0]           = (acc[t][j][0] + b0v) * scale;
            C[(size_t)m0 * N + n0 + 1]       = (acc[t][j][1] + b1v) * scale;
            C[(size_t)(m0 + 8) * N + n0]     = (acc[t][j][2] + b0v) * scale;
            C[(size_t)(m0 + 8) * N + n0 + 1] = (acc[t][j][3] + b1v) * scale;
        }
    }
}

__global__ __launch_bounds__(256) void gemm_nt32_bm_kernel(
    const float* __restrict__ A, const float* __restrict__ B,
    const float* __restrict__ bias, float* __restrict__ C,
    int N, int K) {
    __shared__ float As[2][16 * 136];
    __shared__ float Bs[2][16 * 72];
    int row0 = blockIdx.y * 128, col0 = blockIdx.x * 64;
    int tid = threadIdx.x;
    int w = tid >> 5, lane = tid & 31;
    int wm = w >> 1, wn = w & 1;
    int q = lane >> 2, r4 = lane & 3;
    int am = tid >> 2, akq = (tid & 3) * 4;
    int bn = tid >> 2, bkq = (tid & 3) * 4;

    float acc[2][4][4];
#pragma unroll
    for (int t = 0; t < 2; t++)
#pragma unroll
        for (int j = 0; j < 4; j++)
#pragma unroll
            for (int e = 0; e < 4; e++) acc[t][j][e] = 0.0f;

    float4 av0, av1, bv;
    auto load = [&](int k0) {
        av0 = *(const float4*)(A + (size_t)(row0 + am) * K + k0 + akq);
        av1 = *(const float4*)(A + (size_t)(row0 + am + 64) * K + k0 + akq);
        bv  = *(const float4*)(B + (size_t)(col0 + bn) * K + k0 + bkq);
    };
    auto store = [&](int p) {
        float* Ap = As[p];
        float* Bp = Bs[p];
        Ap[(akq + 0) * 136 + am] = tf32r(av0.x);
        Ap[(akq + 1) * 136 + am] = tf32r(av0.y);
        Ap[(akq + 2) * 136 + am] = tf32r(av0.z);
        Ap[(akq + 3) * 136 + am] = tf32r(av0.w);
        Ap[(akq + 0) * 136 + am + 64] = tf32r(av1.x);
        Ap[(akq + 1) * 136 + am + 64] = tf32r(av1.y);
        Ap[(akq + 2) * 136 + am + 64] = tf32r(av1.z);
        Ap[(akq + 3) * 136 + am + 64] = tf32r(av1.w);
        Bp[(bkq + 0) * 72 + bn] = tf32r(bv.x);
        Bp[(bkq + 1) * 72 + bn] = tf32r(bv.y);
        Bp[(bkq + 2) * 72 + bn] = tf32r(bv.z);
        Bp[(bkq + 3) * 72 + bn] = tf32r(bv.w);
    };

    load(0);
    store(0);
    __syncthreads();
    int p = 0;
    for (int k0 = 0; k0 < K; k0 += 16) {
        bool nxt = (k0 + 16 < K);
        if (nxt) load(k0 + 16);
        const uint32_t* As_u = (const uint32_t*)As[p];
        const uint32_t* Bs_u = (const uint32_t*)Bs[p];
#pragma unroll
        for (int s = 0; s < 2; s++) {
            int kk = s * 8;
            uint32_t a[2][4];
#pragma unroll
            for (int t = 0; t < 2; t++) {
                int mb = wm * 32 + 16 * t + q;
                a[t][0] = As_u[(kk + r4) * 136 + mb];
                a[t][1] = As_u[(kk + r4) * 136 + mb + 8];
                a[t][2] = As_u[(kk + r4 + 4) * 136 + mb];
                a[t][3] = As_u[(kk + r4 + 4) * 136 + mb + 8];
            }
#pragma unroll
            for (int j = 0; j < 4; j++) {
                int nb = wn * 32 + 8 * j + q;
                uint32_t b0 = Bs_u[(kk + r4) * 72 + nb];
                uint32_t b1 = Bs_u[(kk + r4 + 4) * 72 + nb];
#pragma unroll
                for (int t = 0; t < 2; t++)
                    mma_tf32(acc[t][j], a[t][0], a[t][1], a[t][2], a[t][3], b0, b1);
            }
        }
        if (nxt) {
            store(p ^ 1);
            __syncthreads();
        }
        p ^= 1;
    }
#pragma unroll
    for (int t = 0; t < 2; t++) {
#pragma unroll
        for (int j = 0; j < 4; j++) {
            int m0 = row0 + wm * 32 + 16 * t + q;
            int n0 = col0 + wn * 32 + 8 * j + 2 * r4;
            float bm0 = bias[m0], bm8 = bias[m0 + 8];
            C[(size_t)m0 * N + n0]           = acc[t][j][0] + bm0;
            C[(size_t)m0 * N + n0 + 1]       = acc[t][j][1] + bm0;
            C[(size_t)(m0 + 8) * N + n0]     = acc[t][j][2] + bm8;
            C[(size_t)(m0 + 8) * N + n0 + 1] = acc[t][j][3] + bm8;
        }
    }
}

__global__ __launch_bounds__(256) void gemm_nt32_km_kernel(
    const float* __restrict__ A, const float* __restrict__ B,
    const float* __restrict__ bias, float* __restrict__ C,
    int N, int K, int Mtot) {
    __shared__ float As[2][16 * 136];
    __shared__ float Bs[2][16 * 72];
    int row0 = blockIdx.y * 128, col0 = blockIdx.x * 64;
    const float* Ab = A + row0;
    int tid = threadIdx.x;
    int w = tid >> 5, lane = tid & 31;
    int wm = w >> 1, wn = w & 1;
    int q = lane >> 2, r4 = lane & 3;
    int ak = tid >> 5, amq = (tid & 31) << 2;
    int bn = tid >> 2, bkq = (tid & 3) * 4;

    float acc[2][4][4];
#pragma unroll
    for (int t = 0; t < 2; t++)
#pragma unroll
        for (int j = 0; j < 4; j++)
#pragma unroll
            for (int e = 0; e < 4; e++) acc[t][j][e] = 0.0f;

    float4 av0, av1, bv;
    auto load = [&](int k0) {
        av0 = *(const float4*)(Ab + (size_t)(k0 + ak) * Mtot + amq);
        av1 = *(const float4*)(Ab + (size_t)(k0 + ak + 8) * Mtot + amq);
        bv  = *(const float4*)(B + (size_t)(col0 + bn) * K + k0 + bkq);
    };
    auto store = [&](int p) {
        float* Ap = As[p];
        float* Bp = Bs[p];
        Ap[ak * 136 + amq + 0] = tf32r(av0.x);
        Ap[ak * 136 + amq + 1] = tf32r(av0.y);
        Ap[ak * 136 + amq + 2] = tf32r(av0.z);
        Ap[ak * 136 + amq + 3] = tf32r(av0.w);
        Ap[(ak + 8) * 136 + amq + 0] = tf32r(av1.x);
        Ap[(ak + 8) * 136 + amq + 1] = tf32r(av1.y);
        Ap[(ak + 8) * 136 + amq + 2] = tf32r(av1.z);
        Ap[(ak + 8) * 136 + amq + 3] = tf32r(av1.w);
        Bp[(bkq + 0) * 72 + bn] = tf32r(bv.x);
        Bp[(bkq + 1) * 72 + bn] = tf32r(bv.y);
        Bp[(bkq + 2) * 72 + bn] = tf32r(bv.z);
        Bp[(bkq + 3) * 72 + bn] = tf32r(bv.w);
    };

    load(0);
    store(0);
    __syncthreads();
    int p = 0;
    for (int k0 = 0; k0 < K; k0 += 16) {
        bool nxt = (k0 + 16 < K);
        if (nxt) load(k0 + 16);
        const uint32_t* As_u = (const uint32_t*)As[p];
        const uint32_t* Bs_u = (const uint32_t*)Bs[p];
#pragma unroll
        for (int s = 0; s < 2; s++) {
            int kk = s * 8;
            uint32_t a[2][4];
#pragma unroll
            for (int t = 0; t < 2; t++) {
                int mb = wm * 32 + 16 * t + q;
                a[t][0] = As_u[(kk + r4) * 136 + mb];
                a[t][1] = As_u[(kk + r4) * 136 + mb + 8];
                a[t][2] = As_u[(kk + r4 + 4) * 136 + mb];
                a[t][3] = As_u[(kk + r4 + 4) * 136 + mb + 8];
            }
#pragma unroll
            for (int j = 0; j < 4; j++) {
                int nb = wn * 32 + 8 * j + q;
                uint32_t b0 = Bs_u[(kk + r4) * 72 + nb];
                uint32_t b1 = Bs_u[(kk + r4 + 4) * 72 + nb];
#pragma unroll
                for (int t = 0; t < 2; t++)
                    mma_tf32(acc[t][j], a[t][0], a[t][1], a[t][2], a[t][3], b0, b1);
            }
        }
        if (nxt) {
            store(p ^ 1);
            __syncthreads();
        }
        p ^= 1;
    }
#pragma unroll
    for (int t = 0; t < 2; t++) {
#pragma unroll
        for (int j = 0; j < 4; j++) {
            int m0 = row0 + wm * 32 + 16 * t + q;
            int n0 = col0 + wn * 32 + 8 * j + 2 * r4;
            float b0v = bias[n0], b1v = bias[n0 + 1];
            C[(size_t)m0 * N + n0]           = acc[t][j][0] + b0v;
            C[(size_t)m0 * N + n0 + 1]       = acc[t][j][1] + b1v;
            C[(size_t)(m0 + 8) * N + n0]     = acc[t][j][2] + b0v;
            C[(size_t)(m0 + 8) * N + n0 + 1] = acc[t][j][3] + b1v;
        }
    }
}

// ---- center32: depth-2 pipeline with COMPILE-TIME register sets (2x manual unroll) ----
__global__ __launch_bounds__(256) void gemm_center32_kernel(
    const float* __restrict__ cz, const float* __restrict__ x,
    const float* __restrict__ mem, const float* __restrict__ invs,
    float* __restrict__ center) {
    int z = blockIdx.z;
    int b = z >> 2, tau = z & 3;
    const float* A = cz + (size_t)z * 100 * 4096;
    const float* B = (tau < 3) ? (mem + (size_t)(b * 3 + tau) * NN * NC)
                               : (x + (size_t)b * NN * NC);
    float* C = center + (size_t)z * 100 * 256;
    int col0 = blockIdx.x * 64;
    __shared__ float As[2][16 * 136];
    __shared__ float Bs[2][16 * 72];
    int tid = threadIdx.x;
    int w = tid >> 5, lane = tid & 31;
    int wm = w >> 1, wn = w & 1;
    int q = lane >> 2, r4 = lane & 3;
    int am = tid >> 2, akq = (tid & 3) * 4;
    bool a0ok = (am < 100), a1ok = (am + 64 < 100);
    int bk = tid >> 4, bnq = (tid & 15) * 4;

    float acc[2][4][4];
#pragma unroll
    for (int t = 0; t < 2; t++)
#pragma unroll
        for (int j = 0; j < 4; j++)
#pragma unroll
            for (int e = 0; e < 4; e++) acc[t][j][e] = 0.0f;

    // two named register sets (compile-time selection)
    float4 avA0, avA1, bvA;
    float4 avB0, avB1, bvB;
    auto loadA = [&](int k0) {
        avA0 = a0ok ? *(const float4*)(A + (size_t)am * 4096 + k0 + akq) : make_float4(0, 0, 0, 0);
        avA1 = a1ok ? *(const float4*)(A + (size_t)(am + 64) * 4096 + k0 + akq) : make_float4(0, 0, 0, 0);
        bvA  = *(const float4*)(B + (size_t)(k0 + bk) * 256 + col0 + bnq);
    };
    auto loadB = [&](int k0) {
        avB0 = a0ok ? *(const float4*)(A + (size_t)am * 4096 + k0 + akq) : make_float4(0, 0, 0, 0);
        avB1 = a1ok ? *(const float4*)(A + (size_t)(am + 64) * 4096 + k0 + akq) : make_float4(0, 0, 0, 0);
        bvB  = *(const float4*)(B + (size_t)(k0 + bk) * 256 + col0 + bnq);
    };
    auto storeA = [&](int p) {
        float* Ap = As[p];
        float* Bp = Bs[p];
        Ap[(akq + 0) * 136 + am] = tf32r(avA0.x);
        Ap[(akq + 1) * 136 + am] = tf32r(avA0.y);
        Ap[(akq + 2) * 136 + am] = tf32r(avA0.z);
        Ap[(akq + 3) * 136 + am] = tf32r(avA0.w);
        Ap[(akq + 0) * 136 + am + 64] = tf32r(avA1.x);
        Ap[(akq + 1) * 136 + am + 64] = tf32r(avA1.y);
        Ap[(akq + 2) * 136 + am + 64] = tf32r(avA1.z);
        Ap[(akq + 3) * 136 + am + 64] = tf32r(avA1.w);
        Bp[bk * 72 + bnq + 0] = tf32r(bvA.x);
        Bp[bk * 72 + bnq + 1] = tf32r(bvA.y);
        Bp[bk * 72 + bnq + 2] = tf32r(bvA.z);
        Bp[bk * 72 + bnq + 3] = tf32r(bvA.w);
    };
    auto storeB = [&](int p) {
        float* Ap = As[p];
        float* Bp = Bs[p];
        Ap[(akq + 0) * 136 + am] = tf32r(avB0.x);
        Ap[(akq + 1) * 136 + am] = tf32r(avB0.y);
        Ap[(akq + 2) * 136 + am] = tf32r(avB0.z);
        Ap[(akq + 3) * 136 + am] = tf32r(avB0.w);
        Ap[(akq + 0) * 136 + am + 64] = tf32r(avB1.x);
        Ap[(akq + 1) * 136 + am + 64] = tf32r(avB1.y);
        Ap[(akq + 2) * 136 + am + 64] = tf32r(avB1.z);
        Ap[(akq + 3) * 136 + am + 64] = tf32r(avB1.w);
        Bp[bk * 72 + bnq + 0] = tf32r(bvB.x);
        Bp[bk * 72 + bnq + 1] = tf32r(bvB.y);
        Bp[bk * 72 + bnq + 2] = tf32r(bvB.z);
        Bp[bk * 72 + bnq + 3] = tf32r(bvB.w);
    };
    auto compute = [&](int p) {
        const uint32_t* As_u = (const uint32_t*)As[p];
        const uint32_t* Bs_u = (const uint32_t*)Bs[p];
#pragma unroll
        for (int s = 0; s < 2; s++) {
            int kk = s * 8;
            uint32_t a[2][4];
#pragma unroll
            for (int t = 0; t < 2; t++) {
                int mb = wm * 32 + 16 * t + q;
                a[t][0] = As_u[(kk + r4) * 136 + mb];
                a[t][1] = As_u[(kk + r4) * 136 + mb + 8];
                a[t][2] = As_u[(kk + r4 + 4) * 136 + mb];
                a[t][3] = As_u[(kk + r4 + 4) * 136 + mb + 8];
            }
#pragma unroll
            for (int j = 0; j < 4; j++) {
                int nb = wn * 32 + 8 * j + q;
                uint32_t b0 = Bs_u[(kk + r4) * 72 + nb];
                uint32_t b1 = Bs_u[(kk + r4 + 4) * 72 + nb];
#pragma unroll
                for (int t = 0; t < 2; t++)
                    mma_tf32(acc[t][j], a[t][0], a[t][1], a[t][2], a[t][3], b0, b1);
            }
        }
    };

    // prologue: data0 -> setA -> smem buf0; data1 -> setB
    loadA(0);
    storeA(0);
    loadB(16);
    __syncthreads();
    int p = 0;
    for (int it = 0; it < 256; it += 2) {
        // even iteration it: load data it+2 into setA, compute buf p, store data it+1 (setB)
        if (it + 2 < 256) loadA((it + 2) << 4);
        compute(p);
        if (it + 1 < 256) {
            storeB(p ^ 1);
            __syncthreads();
        }
        p ^= 1;
        // odd iteration it+1: load data it+3 into setB, compute buf p, store data it+2 (setA)
        if (it + 3 < 256) loadB((it + 3) << 4);
        compute(p);
        if (it + 2 < 256) {
            storeA(p ^ 1);
            __syncthreads();
        }
        p ^= 1;
    }
#pragma unroll
    for (int t = 0; t < 2; t++) {
#pragma unroll
        for (int j = 0; j < 4; j++) {
            int m0 = wm * 32 + 16 * t + q;
            int n0 = col0 + wn * 32 + 8 * j + 2 * r4;
            if (m0 < 100) {
                float iv = invs[z * 100 + m0];
                C[(size_t)m0 * 256 + n0]     = acc[t][j][0] * iv;
                C[(size_t)m0 * 256 + n0 + 1] = acc[t][j][1] * iv;
            }
            if (m0 + 8 < 100) {
                float iv = invs[z * 100 + m0 + 8];
                C[(size_t)(m0 + 8) * 256 + n0]     = acc[t][j][2] * iv;
                C[(size_t)(m0 + 8) * 256 + n0 + 1] = acc[t][j][3] * iv;
            }
        }
    }
}

// ---------------- k/v merged fp32 GEMM ----------------
__global__ __launch_bounds__(256) void gemm_nt_kv_kernel(
    const float* __restrict__ A, const float* __restrict__ kw,
    const float* __restrict__ kbias, const float* __restrict__ vw,
    const float* __restrict__ vbias, float* __restrict__ Ck, float* __restrict__ Cv) {
    const float* B = blockIdx.z ? vw : kw;
    const float* bias = blockIdx.z ? vbias : kbias;
    float* C = blockIdx.z ? Cv : Ck;
    const int M = 400, N = 256, K = 256;
    __shared__ float As[16][68];
    __shared__ float Bs[16][68];
    int tid = threadIdx.x;
    int tx = tid & 15, ty = tid >> 4;
    int row0 = blockIdx.y * 64, col0 = blockIdx.x * 64;
    int lr = tid >> 2;
    int lk = (tid & 3) << 2;
    const float* Aptr = A + (size_t)(row0 + lr) * K + lk;
    const float* Bptr = B + (size_t)(col0 + lr) * K + lk;
    bool aok = (row0 + lr) < M;
    float acc[4][4];
#pragma unroll
    for (int i = 0; i < 4; i++)
#pragma unroll
        for (int j = 0; j < 4; j++) acc[i][j] = 0.0f;

    for (int k0 = 0; k0 < K; k0 += 16) {
        float4 av = aok ? *(const float4*)(Aptr + k0) : make_float4(0, 0, 0, 0);
        float4 bv = *(const float4*)(Bptr + k0);
        As[lk + 0][lr] = av.x; As[lk + 1][lr] = av.y; As[lk + 2][lr] = av.z; As[lk + 3][lr] = av.w;
        Bs[lk + 0][lr] = bv.x; Bs[lk + 1][lr] = bv.y; Bs[lk + 2][lr] = bv.z; Bs[lk + 3][lr] = bv.w;
        __syncthreads();
#pragma unroll
        for (int kk = 0; kk < 16; kk++) {
            float4 a = *(const float4*)&As[kk][ty * 4];
            float4 b = *(const float4*)&Bs[kk][tx * 4];
            float aa[4] = {a.x, a.y, a.z, a.w};
            float bb[4] = {b.x, b.y, b.z, b.w};
#pragma unroll
            for (int i = 0; i < 4; i++)
#pragma unroll
                for (int j = 0; j < 4; j++) acc[i][j] += aa[i] * bb[j];
        }
        __syncthreads();
    }
#pragma unroll
    for (int i = 0; i < 4; i++) {
        int m = row0 + ty * 4 + i;
        if (m < M) {
#pragma unroll
            for (int j = 0; j < 4; j++) {
                int n = col0 + tx * 4 + j;
                C[(size_t)m * N + n] = acc[i][j] + bias[n];
            }
        }
    }
}

// ---------------- softmax: single pass ----------------
__global__ void softmax_exp_kernel(float* __restrict__ data, float* __restrict__ invs) {
    __shared__ float sh[8];
    float4* row = (float4*)(data + (size_t)blockIdx.x * 4096);
    int tid = threadIdx.x;
    float s = 0.0f;
    for (int i = tid; i < 1024; i += 256) {
        float4 v = row[i];
        v.x = __expf(v.x);
        v.y = __expf(v.y);
        v.z = __expf(v.z);
        v.w = __expf(v.w);
        row[i] = v;
        s += v.x + v.y + v.z + v.w;
    }
    s = blockReduceSum(s, sh);
    if (tid == 0) invs[blockIdx.x] = 1.0f / s;
}

// ---------------- cosine gating + C_in + LN ----------------
__global__ void cos_cin_kernel(const float* __restrict__ center,
                               const float* __restrict__ alpha, const float* __restrict__ beta,
                               const float* __restrict__ lnw, const float* __restrict__ lnb,
                               float* __restrict__ cin) {
    __shared__ float sh[8];
    int bk = blockIdx.x;
    int b = bk / 100, k = bk - b * 100;
    int c = threadIdx.x;
    const float* base = center + ((size_t)b * 4 * 100 + k) * 256 + c;
    float p0 = base[0];
    float p1 = base[100 * 256];
    float p2 = base[2 * 100 * 256];
    float last = base[3 * 100 * 256];

    float nl = blockReduceSum(last * last, sh);
    float n0 = blockReduceSum(p0 * p0, sh);
    float n1 = blockReduceSum(p1 * p1, sh);
    float n2 = blockReduceSum(p2 * p2, sh);
    float d0 = blockReduceSum(last * p0, sh);
    float d1 = blockReduceSum(last * p1, sh);
    float d2 = blockReduceSum(last * p2, sh);

    float a = alpha[0], be = beta[0];
    float nls = sqrtf(nl);
    float c0 = sigmoid_f(be + a * (d0 / fmaxf(nls * sqrtf(n0), 1e-8f)));
    float c1 = sigmoid_f(be + a * (d1 / fmaxf(nls * sqrtf(n1), 1e-8f)));
    float c2 = sigmoid_f(be + a * (d2 / fmaxf(nls * sqrtf(n2), 1e-8f)));

    float v = last + c0 * p0 + c1 * p1 + c2 * p2;
    float mean = blockReduceSum(v, sh) * (1.0f / 256.0f);
    float d = v - mean;
    float var = blockReduceSum(d * d, sh) * (1.0f / 256.0f);
    cin[((size_t)b * 100 + k) * 256 + c] = d * rsqrtf(var + 1e-5f) * lnw[c] + lnb[c];
}

// ---------------- attention ----------------
__global__ __launch_bounds__(256) void attn_kernel(const float* __restrict__ q,
                                                   const float* __restrict__ k,
                                                   const float* __restrict__ v,
                                                   float* __restrict__ o) {
    __shared__ float ks[100 * 32];
    __shared__ float vs[100 * 32];
    int b = blockIdx.z, h = blockIdx.y;
    int n = blockIdx.x * 256 + threadIdx.x;
    int tid = threadIdx.x;
    for (int e = tid; e < 3200; e += 256) {
        int kk = e >> 5, d = e & 31;
        ks[kk * 32 + d] = k[((size_t)b * 100 + kk) * 256 + h * 32 + d];
        vs[kk * 32 + d] = v[((size_t)b * 100 + kk) * 256 + h * 32 + d];
    }
    __syncthreads();
    float qr[32];
    const float4* qp4 = (const float4*)(q + ((size_t)b * 4096 + n) * 256 + h * 32);
#pragma unroll
    for (int i = 0; i < 8; i++) {
        float4 vv = qp4[i];
        qr[4 * i] = vv.x; qr[4 * i + 1] = vv.y; qr[4 * i + 2] = vv.z; qr[4 * i + 3] = vv.w;
    }
    float m = -3.4e38f;
    for (int kk = 0; kk < 100; kk++) {
        float s = 0.0f;
#pragma unroll
        for (int d = 0; d < 32; d++) s += qr[d] * ks[kk * 32 + d];
        m = fmaxf(m, s);
    }
    float sum = 0.0f;
    float acc[32];
#pragma unroll
    for (int d = 0; d < 32; d++) acc[d] = 0.0f;
    for (int kk = 0; kk < 100; kk++) {
        float s = 0.0f;
#pragma unroll
        for (int d = 0; d < 32; d++) s += qr[d] * ks[kk * 32 + d];
        float e = __expf(s - m);
        sum += e;
#pragma unroll
        for (int d = 0; d < 32; d++) acc[d] += e * vs[kk * 32 + d];
    }
    float inv = 1.0f / sum;
    float4* op4 = (float4*)(o + ((size_t)b * 4096 + n) * 256 + h * 32);
#pragma unroll
    for (int i = 0; i < 8; i++)
        op4[i] = make_float4(acc[4 * i] * inv, acc[4 * i + 1] * inv,
                             acc[4 * i + 2] * inv, acc[4 * i + 3] * inv);
}

// ---------------- out = base + LN(p) ----------------
__global__ void add_ln_kernel(const float* __restrict__ base, const float* __restrict__ p,
                              const float* __restrict__ w, const float* __restrict__ bb,
                              float* __restrict__ out) {
    __shared__ float sh[8];
    int t = threadIdx.x;
    int lr = t >> 6;
    int cq = (t & 63) << 2;
    size_t row = (size_t)blockIdx.x * 4 + lr;
    int wid = t >> 5, lane = t & 31;

    float4 v = *(const float4*)(p + row * 256 + cq);
    float s = v.x + v.y + v.z + v.w;
    s = warpReduceSum(s);
    if (lane == 0) sh[wid] = s;
    __syncthreads();
    float mean = (sh[2 * lr] + sh[2 * lr + 1]) * (1.0f / 256.0f);
    float4 d;
    d.x = v.x - mean; d.y = v.y - mean; d.z = v.z - mean; d.w = v.w - mean;
    float ss = d.x * d.x + d.y * d.y + d.z * d.z + d.w * d.w;
    ss = warpReduceSum(ss);
    __syncthreads();
    if (lane == 0) sh[wid] = ss;
    __syncthreads();
    float var = (sh[2 * lr] + sh[2 * lr + 1]) * (1.0f / 256.0f);
    float inv = rsqrtf(var + 1e-5f);
    float4 wv = *(const float4*)(w + cq);
    float4 bv = *(const float4*)(bb + cq);
    float4 basev = *(const float4*)(base + row * 256 + cq);
    float4 r;
    r.x = basev.x + d.x * inv * wv.x + bv.x;
    r.y = basev.y + d.y * inv * wv.y + bv.y;
    r.z = basev.z + d.z * inv * wv.z + bv.z;
    r.w = basev.w + d.w * inv * wv.w + bv.w;
    *(float4*)(out + row * 256 + cq) = r;
}

// ---------------- depthwise 3x3 on (ch, B*4096): smem plane tile + float4 ----------------
__global__ __launch_bounds__(256) void dwconv_kernel(const float* __restrict__ in,
                                                     const float* __restrict__ w,
                                                     const float* __restrict__ bias,
                                                     float* __restrict__ out) {
    __shared__ float t[66 * 68];
    int plane = blockIdx.x;
    int ch = plane & 1023;
    int b = plane >> 10;
    const float* ip = in + (size_t)ch * 16384 + b * 4096;
    float* op = out + (size_t)ch * 16384 + b * 4096;
    int tid = threadIdx.x;

    float4 z4 = make_float4(0.f, 0.f, 0.f, 0.f);
    for (int e = tid; e < 1122; e += 256) ((float4*)t)[e] = z4;
    __syncthreads();
#pragma unroll
    for (int i = 0; i < 4; i++) {
        int idx = tid + i * 256;
        int y = idx >> 4;
        int x4 = (idx & 15) << 2;
        float4 vv = *(const float4*)(ip + y * 64 + x4);
        float* dst = &t[(y + 1) * 68 + 1 + x4];
        dst[0] = vv.x; dst[1] = vv.y; dst[2] = vv.z; dst[3] = vv.w;
    }
    float wr[9];
#pragma unroll
    for (int i = 0; i < 9; i++) wr[i] = w[ch * 9 + i];
    float bi = bias[ch];
    __syncthreads();

#pragma unroll
    for (int i = 0; i < 4; i++) {
        int idx = tid + i * 256;
        int y = idx >> 4;
        int x4 = (idx & 15) << 2;
        float r[4];
#pragma unroll
        for (int j = 0; j < 4; j++) {
            int x = x4 + j;
            float s = bi;
#pragma unroll
            for (int dy = 0; dy < 3; dy++)
#pragma unroll
                for (int dx = 0; dx < 3; dx++)
                    s += t[(y + dy) * 68 + x + dx] * wr[dy * 3 + dx];
            r[j] = gelu_f(s);
        }
        *(float4*)(op + y * 64 + x4) = make_float4(r[0], r[1], r[2], r[3]);
    }
}

// ---------------- host launcher ----------------
extern "C" void kernel_launch(void* const* d_in, const int* in_sizes, int n_in,
                              void* d_out, int out_size) {
    const float* x       = (const float*)d_in[0];
    const float* mem     = (const float*)d_in[1];
    const float* conv1_w = (const float*)d_in[2];
    const float* conv1_b = (const float*)d_in[3];
    const float* conv2_w = (const float*)d_in[4];
    const float* conv2_b = (const float*)d_in[5];
    const float* conv3_w = (const float*)d_in[6];
    const float* sim_a   = (const float*)d_in[7];
    const float* sim_b   = (const float*)d_in[8];
    const float* ln_w    = (const float*)d_in[9];
    const float* ln_b    = (const float*)d_in[10];
    const float* q_w     = (const float*)d_in[11];
    const float* q_b     = (const float*)d_in[12];
    const float* k_w     = (const float*)d_in[13];
    const float* k_b     = (const float*)d_in[14];
    const float* v_w     = (const float*)d_in[15];
    const float* v_b     = (const float*)d_in[16];
    const float* proj_w  = (const float*)d_in[17];
    const float* proj_b  = (const float*)d_in[18];
    const float* fc1_w   = (const float*)d_in[19];
    const float* fc1_b   = (const float*)d_in[20];
    const float* dw_w    = (const float*)d_in[21];
    const float* dw_b    = (const float*)d_in[22];
    const float* fc2_w   = (const float*)d_in[23];
    const float* fc2_b   = (const float*)d_in[24];
    float* out = (float*)d_out;

    float *img, *h, *cz, *center, *cin, *kb, *vb, *qb, *ob, *outb, *invs;
    uint32_t *img2, *h2, *w1t2, *w2p2, *w3p2;
    cudaGetSymbolAddress((void**)&img, g_img);
    cudaGetSymbolAddress((void**)&h, g_h);
    cudaGetSymbolAddress((void**)&cz, g_cz);
    cudaGetSymbolAddress((void**)&img2, g_img2);
    cudaGetSymbolAddress((void**)&h2, g_h2);
    cudaGetSymbolAddress((void**)&w1t2, g_w1t2);
    cudaGetSymbolAddress((void**)&w2p2, g_w2p2);
    cudaGetSymbolAddress((void**)&w3p2, g_w3p2);
    cudaGetSymbolAddress((void**)&invs, g_invs);
    cudaGetSymbolAddress((void**)&center, g_center);
    cudaGetSymbolAddress((void**)&cin, g_cin);
    cudaGetSymbolAddress((void**)&kb, g_kb);
    cudaGetSymbolAddress((void**)&vb, g_vb);
    cudaGetSymbolAddress((void**)&qb, g_qb);
    cudaGetSymbolAddress((void**)&ob, g_ob);
    cudaGetSymbolAddress((void**)&outb, g_outb);

    // 1: w1 pack (coalesced), 2: w2/w3 pack, 3: input pack, 4: conv1 (clock probe)
    w1_pack_kernel<<<dim3(8, 32), 256>>>(conv1_w, w1t2);
    pack23_kernel<<<192, 256>>>(conv2_w, conv3_w, w2p2, w3p2);
    build_img2_kernel<<<dim3(128, 8, 16), dim3(32, 8)>>>(x, mem, img2);
    cudaFuncSetAttribute(conv1_mma_kernel, cudaFuncAttributeMaxDynamicSharedMemorySize, CONV1_SMEM);
    conv1_mma_kernel<<<dim3(4, 16, 16), 256, CONV1_SMEM>>>(img2, w1t2, conv1_b, h2);
    gemm1x1_bf16_kernel<0><<<dim3(4, 16, 16), 256>>>(h2, w2p2, conv2_b, (void*)img2, 256);
    gemm1x1_bf16_kernel<1><<<dim3(2, 16, 16), 256>>>(img2, w3p2, (const float*)0, (void*)cz, 128);
    softmax_exp_kernel<<<1600, 256>>>(cz, invs);
    gemm_center32_kernel<<<dim3(4, 1, 16), 256>>>(cz, x, mem, invs, center);
    cos_cin_kernel<<<400, 256>>>(center, sim_a, sim_b, ln_w, ln_b, cin);
    gemm_nt32_kernel<<<dim3(4, 128), 256>>>(x, q_w, q_b, qb, 256, 256, 0.17677669529663687f);
    gemm_nt_kv_kernel<<<dim3(4, 7, 2), 256>>>(cin, k_w, k_b, v_w, v_b, kb, vb);
    attn_kernel<<<dim3(16, 8, 4), 256>>>(qb, kb, vb, ob);
    gemm_nt32_kernel<<<dim3(4, 128), 256>>>(ob, proj_w, proj_b, qb, 256, 256, 1.0f);
    add_ln_kernel<<<4096, 256>>>(x, qb, ln_w, ln_b, outb);
    gemm_nt32_bm_kernel<<<dim3(256, 8), 256>>>(fc1_w, outb, fc1_b, h, 16384, 256);
    dwconv_kernel<<<4096, 256>>>(h, dw_w, dw_b, img);
    gemm_nt32_km_kernel<<<dim3(4, 128), 256>>>(img, fc2_w, fc2_b, qb, 256, 1024, 16384);
    add_ln_kernel<<<4096, 256>>>(outb, qb, ln_w, ln_b, out);
}